// round 13
// baseline (speedup 1.0000x reference)
#include <cuda_runtime.h>
#include <cuda_bf16.h>
#include <cuda_fp16.h>
#include <cstdint>

#define BATCH 4
#define CH    512
#define HW    4096
#define AD    512

typedef __nv_bfloat16 bf16;

// ---------------- scratch (__device__ globals; no allocation) ---------------
__device__ bf16 g_xth[BATCH * HW * CH];          // x^T [b][n][c] hi
__device__ bf16 g_xtl[BATCH * HW * CH];          // lo
__device__ bf16 g_wh[3 * AD * CH];               // Wq,Wk,Wv hi
__device__ bf16 g_wl[3 * AD * CH];               // lo
__device__ bf16 g_qh[BATCH * HW * AD];
__device__ bf16 g_ql[BATCH * HW * AD];
__device__ bf16 g_kh[BATCH * HW * AD];
__device__ bf16 g_kl[BATCH * HW * AD];
__device__ __half g_vt16[BATCH * CH * HW];       // v^T [b][c][n], fp16
__device__ float g_S[(size_t)BATCH * HW * HW];   // scores fp32
__device__ __half g_p16[(size_t)BATCH * HW * HW]; // softmax probs fp16
__device__ float g_cmax[BATCH * 32 * HW];        // per-row-tile column max
__device__ float g_csum[BATCH * 32 * HW];        // per-row-tile column sumexp

// ---------------- helpers ----------------------------------------------------
__device__ __forceinline__ uint32_t smem_u32(const void* p) {
    uint32_t a;
    asm("{ .reg .u64 t; cvta.to.shared.u64 t, %1; cvt.u32.u64 %0, t; }" : "=r"(a) : "l"(p));
    return a;
}
__device__ __forceinline__ void cp16(uint32_t d, const void* s) {
    asm volatile("cp.async.ca.shared.global [%0], [%1], 16;" :: "r"(d), "l"(s));
}
__device__ __forceinline__ void cp_commit() { asm volatile("cp.async.commit_group;" ::: "memory"); }
__device__ __forceinline__ void cp_wait0()  { asm volatile("cp.async.wait_group 0;" ::: "memory"); }
__device__ __forceinline__ void cp_wait1()  { asm volatile("cp.async.wait_group 1;" ::: "memory"); }
__device__ __forceinline__ void cp_wait2()  { asm volatile("cp.async.wait_group 2;" ::: "memory"); }

__device__ __forceinline__ void ldsm4(uint32_t* r, uint32_t addr) {
    asm volatile("ldmatrix.sync.aligned.m8n8.x4.shared.b16 {%0,%1,%2,%3}, [%4];"
        : "=r"(r[0]), "=r"(r[1]), "=r"(r[2]), "=r"(r[3]) : "r"(addr));
}

__device__ __forceinline__ void mma16816(float* c,
    uint32_t a0, uint32_t a1, uint32_t a2, uint32_t a3, uint32_t b0, uint32_t b1)
{
    asm volatile(
        "mma.sync.aligned.m16n8k16.row.col.f32.bf16.bf16.f32 "
        "{%0,%1,%2,%3},{%4,%5,%6,%7},{%8,%9},{%0,%1,%2,%3};"
        : "+f"(c[0]), "+f"(c[1]), "+f"(c[2]), "+f"(c[3])
        : "r"(a0), "r"(a1), "r"(a2), "r"(a3), "r"(b0), "r"(b1));
}
__device__ __forceinline__ void mma16816h(float* c,
    uint32_t a0, uint32_t a1, uint32_t a2, uint32_t a3, uint32_t b0, uint32_t b1)
{
    asm volatile(
        "mma.sync.aligned.m16n8k16.row.col.f32.f16.f16.f32 "
        "{%0,%1,%2,%3},{%4,%5,%6,%7},{%8,%9},{%0,%1,%2,%3};"
        : "+f"(c[0]), "+f"(c[1]), "+f"(c[2]), "+f"(c[3])
        : "r"(a0), "r"(a1), "r"(a2), "r"(a3), "r"(b0), "r"(b1));
}

// FMA-only exp (x <= 0)
__device__ __forceinline__ float fast_exp_neg(float x) {
    float t = x * 1.4426950408889634f;
    t = fmaxf(t, -126.0f);
    float r = rintf(t);
    float f = t - r;
    float p = 1.3333558e-3f;
    p = fmaf(p, f, 9.6181291e-3f);
    p = fmaf(p, f, 5.5504110e-2f);
    p = fmaf(p, f, 2.4022651e-1f);
    p = fmaf(p, f, 6.9314718e-1f);
    p = fmaf(p, f, 1.0f);
    return __int_as_float(__float_as_int(p) + ((int)r << 23));
}

__device__ __forceinline__ void split2(float v, bf16& h, bf16& l) {
    h = __float2bfloat16(v);
    l = __float2bfloat16(v - __bfloat162float(h));
}

// ---------------- proj smem layout: K=32 stages, double-buffered --------------
#define TT      40
#define TILE_H  5120
#define TILE_B  10240
#define STAGE_H 20480
#define STAGE_B 40960
#define SMEM_GEMM (2 * STAGE_B)   // 81920

__device__ __forceinline__ void stage_load32(uint32_t sb, int st,
    const bf16* __restrict__ Ah, const bf16* __restrict__ Al,
    const bf16* __restrict__ Bh, const bf16* __restrict__ Bl,
    int ldA, int ldB, int k0, int tid)
{
    int row = tid >> 1;
    int h0  = (tid & 1) * 16;
    uint32_t d = sb + st * STAGE_B + row * 80 + h0 * 2;
    const size_t oA = (size_t)row * ldA + k0 + h0;
    const size_t oB = (size_t)row * ldB + k0 + h0;
    cp16(d + 0 * TILE_B,      Ah + oA); cp16(d + 0 * TILE_B + 16, Ah + oA + 8);
    cp16(d + 1 * TILE_B,      Al + oA); cp16(d + 1 * TILE_B + 16, Al + oA + 8);
    cp16(d + 2 * TILE_B,      Bh + oB); cp16(d + 2 * TILE_B + 16, Bh + oB + 8);
    cp16(d + 3 * TILE_B,      Bl + oB); cp16(d + 3 * TILE_B + 16, Bl + oB + 8);
    cp_commit();
}

__device__ __forceinline__ void stage_mma32(uint32_t sst, float acc[4][4][4],
                                            int wm, int wn, int lane)
{
    int lane8 = lane & 7, seg = lane >> 3;
    int arow = (seg & 1) << 3, acol = (seg >> 1) << 3;
    int brow = (seg >> 1) << 3, bcol = (seg & 1) << 3;

    #pragma unroll
    for (int kh = 0; kh < 2; kh++) {
        int ko = kh * 16;
        uint32_t ah[4][4], bh[4][2];
        #pragma unroll
        for (int i = 0; i < 4; i++) {
            int r = wm * 64 + i * 16 + lane8 + arow;
            ldsm4(ah[i], sst + 0 * TILE_B + (uint32_t)(r * TT + ko + acol) * 2);
        }
        #pragma unroll
        for (int jp = 0; jp < 2; jp++) {
            int r = wn * 32 + jp * 16 + lane8 + brow;
            uint32_t t[4];
            ldsm4(t, sst + 2 * TILE_B + (uint32_t)(r * TT + ko + bcol) * 2);
            bh[jp * 2][0] = t[0];     bh[jp * 2][1] = t[1];
            bh[jp * 2 + 1][0] = t[2]; bh[jp * 2 + 1][1] = t[3];
        }
        #pragma unroll
        for (int i = 0; i < 4; i++)
            #pragma unroll
            for (int j = 0; j < 4; j++)
                mma16816(acc[i][j], ah[i][0], ah[i][1], ah[i][2], ah[i][3], bh[j][0], bh[j][1]);

        uint32_t bl[4][2];
        #pragma unroll
        for (int jp = 0; jp < 2; jp++) {
            int r = wn * 32 + jp * 16 + lane8 + brow;
            uint32_t t[4];
            ldsm4(t, sst + 3 * TILE_B + (uint32_t)(r * TT + ko + bcol) * 2);
            bl[jp * 2][0] = t[0];     bl[jp * 2][1] = t[1];
            bl[jp * 2 + 1][0] = t[2]; bl[jp * 2 + 1][1] = t[3];
        }
        #pragma unroll
        for (int i = 0; i < 4; i++)
            #pragma unroll
            for (int j = 0; j < 4; j++)
                mma16816(acc[i][j], ah[i][0], ah[i][1], ah[i][2], ah[i][3], bl[j][0], bl[j][1]);

        uint32_t al[4][4];
        #pragma unroll
        for (int i = 0; i < 4; i++) {
            int r = wm * 64 + i * 16 + lane8 + arow;
            ldsm4(al[i], sst + 1 * TILE_B + (uint32_t)(r * TT + ko + acol) * 2);
        }
        #pragma unroll
        for (int i = 0; i < 4; i++)
            #pragma unroll
            for (int j = 0; j < 4; j++)
                mma16816(acc[i][j], al[i][0], al[i][1], al[i][2], al[i][3], bh[j][0], bh[j][1]);
    }
}

#define MMA_PROLOG()                                                             \
    extern __shared__ char smc[];                                                \
    uint32_t sb = smem_u32(smc);                                                 \
    int tid = threadIdx.x, lane = tid & 31, wid = tid >> 5;                      \
    int wm = wid & 1, wn = wid >> 1, g = lane >> 2, tg = lane & 3;               \
    float acc[4][4][4];                                                          \
    _Pragma("unroll")                                                            \
    for (int i = 0; i < 4; i++)                                                  \
        _Pragma("unroll")                                                        \
        for (int j = 0; j < 4; j++)                                              \
            _Pragma("unroll")                                                    \
            for (int r = 0; r < 4; r++) acc[i][j][r] = 0.f;

// ---------------- scores smem layout: K=16 stages, 4-deep, TT=24 -------------
#define TTS        24            // 12 words: LDSM banks r*12 mod 32 distinct
#define SC_TILE_B  6144          // 128*24*2
#define SC_STAGE_B 24576         // 4 tiles
#define SC_SMEM    (4 * SC_STAGE_B)   // 98304 -> 2 CTA/SM

__device__ __forceinline__ void stage_load16s(uint32_t sb, int st,
    const bf16* __restrict__ Ah, const bf16* __restrict__ Al,
    const bf16* __restrict__ Bh, const bf16* __restrict__ Bl,
    int ldA, int ldB, int k0, int tid)
{
    int row = tid >> 1;
    int h0  = (tid & 1) * 8;
    uint32_t d = sb + st * SC_STAGE_B + row * 48 + h0 * 2;
    const size_t oA = (size_t)row * ldA + k0 + h0;
    const size_t oB = (size_t)row * ldB + k0 + h0;
    cp16(d + 0 * SC_TILE_B, Ah + oA);
    cp16(d + 1 * SC_TILE_B, Al + oA);
    cp16(d + 2 * SC_TILE_B, Bh + oB);
    cp16(d + 3 * SC_TILE_B, Bl + oB);
    cp_commit();
}

__device__ __forceinline__ void stage_mma16s(uint32_t sst, float acc[4][4][4],
                                             int wm, int wn, int lane)
{
    int lane8 = lane & 7, seg = lane >> 3;
    int arow = (seg & 1) << 3, acol = (seg >> 1) << 3;
    int brow = (seg >> 1) << 3, bcol = (seg & 1) << 3;

    uint32_t ah[4][4], bh[4][2];
    #pragma unroll
    for (int i = 0; i < 4; i++) {
        int r = wm * 64 + i * 16 + lane8 + arow;
        ldsm4(ah[i], sst + 0 * SC_TILE_B + (uint32_t)(r * TTS + acol) * 2);
    }
    #pragma unroll
    for (int jp = 0; jp < 2; jp++) {
        int r = wn * 32 + jp * 16 + lane8 + brow;
        uint32_t t[4];
        ldsm4(t, sst + 2 * SC_TILE_B + (uint32_t)(r * TTS + bcol) * 2);
        bh[jp * 2][0] = t[0];     bh[jp * 2][1] = t[1];
        bh[jp * 2 + 1][0] = t[2]; bh[jp * 2 + 1][1] = t[3];
    }
    #pragma unroll
    for (int i = 0; i < 4; i++)
        #pragma unroll
        for (int j = 0; j < 4; j++)
            mma16816(acc[i][j], ah[i][0], ah[i][1], ah[i][2], ah[i][3], bh[j][0], bh[j][1]);

    uint32_t bl[4][2];
    #pragma unroll
    for (int jp = 0; jp < 2; jp++) {
        int r = wn * 32 + jp * 16 + lane8 + brow;
        uint32_t t[4];
        ldsm4(t, sst + 3 * SC_TILE_B + (uint32_t)(r * TTS + bcol) * 2);
        bl[jp * 2][0] = t[0];     bl[jp * 2][1] = t[1];
        bl[jp * 2 + 1][0] = t[2]; bl[jp * 2 + 1][1] = t[3];
    }
    #pragma unroll
    for (int i = 0; i < 4; i++)
        #pragma unroll
        for (int j = 0; j < 4; j++)
            mma16816(acc[i][j], ah[i][0], ah[i][1], ah[i][2], ah[i][3], bl[j][0], bl[j][1]);

    uint32_t al[4][4];
    #pragma unroll
    for (int i = 0; i < 4; i++) {
        int r = wm * 64 + i * 16 + lane8 + arow;
        ldsm4(al[i], sst + 1 * SC_TILE_B + (uint32_t)(r * TTS + acol) * 2);
    }
    #pragma unroll
    for (int i = 0; i < 4; i++)
        #pragma unroll
        for (int j = 0; j < 4; j++)
            mma16816(acc[i][j], al[i][0], al[i][1], al[i][2], al[i][3], bh[j][0], bh[j][1]);
}

// ---------------- k_out smem layout: fp16, 2 tiles, K=64, 3-deep pipeline ----
#define TTO        72
#define OT_TILE_H  9216
#define OT_TILE_B  18432
#define OT_STAGE_B 36864
#define OT_SMEM    (3 * OT_STAGE_B)   // 110592 -> 2 CTA/SM

__device__ __forceinline__ void stage_load_o64(uint32_t sb, int st,
    const __half* __restrict__ A, const __half* __restrict__ B,
    int ldA, int ldB, int k0, int tid)
{
    int row = tid >> 1;
    int seg = tid & 1;
    uint32_t d = sb + st * OT_STAGE_B + row * 144 + seg * 64;
    const size_t oA = (size_t)row * ldA + k0 + seg * 32;
    const size_t oB = (size_t)row * ldB + k0 + seg * 32;
    #pragma unroll
    for (int u = 0; u < 4; u++) {
        cp16(d + u * 16,              A + oA + u * 8);
        cp16(d + OT_TILE_B + u * 16,  B + oB + u * 8);
    }
    cp_commit();
}

__device__ __forceinline__ void stage_mma_o64(uint32_t sst, float acc[4][4][4],
                                              int wm, int wn, int lane)
{
    int lane8 = lane & 7, seg = lane >> 3;
    int arow = (seg & 1) << 3, acol = (seg >> 1) << 3;
    int brow = (seg >> 1) << 3, bcol = (seg & 1) << 3;

    #pragma unroll
    for (int kh = 0; kh < 4; kh++) {
        int ko = kh * 16;
        uint32_t a[4][4], b[4][2];
        #pragma unroll
        for (int i = 0; i < 4; i++) {
            int r = wm * 64 + i * 16 + lane8 + arow;
            ldsm4(a[i], sst + (uint32_t)(r * TTO + ko + acol) * 2);
        }
        #pragma unroll
        for (int jp = 0; jp < 2; jp++) {
            int r = wn * 32 + jp * 16 + lane8 + brow;
            uint32_t t[4];
            ldsm4(t, sst + OT_TILE_B + (uint32_t)(r * TTO + ko + bcol) * 2);
            b[jp * 2][0] = t[0];     b[jp * 2][1] = t[1];
            b[jp * 2 + 1][0] = t[2]; b[jp * 2 + 1][1] = t[3];
        }
        #pragma unroll
        for (int i = 0; i < 4; i++)
            #pragma unroll
            for (int j = 0; j < 4; j++)
                mma16816h(acc[i][j], a[i][0], a[i][1], a[i][2], a[i][3], b[j][0], b[j][1]);
    }
}

// ---------------------------------------------------------------------------
// K0a: x [b][c][n] -> transposed split xt hi/lo [b][n][c]
// ---------------------------------------------------------------------------
__global__ __launch_bounds__(256) void k_split_x(const float* __restrict__ x)
{
    __shared__ float t[32][33];
    int b = blockIdx.z;
    int n0 = blockIdx.x * 32, c0 = blockIdx.y * 32;
    int tx = threadIdx.x & 31, ty = threadIdx.x >> 5;

    const float* xb = x + (size_t)b * CH * HW;
    #pragma unroll
    for (int k = 0; k < 4; k++)
        t[ty + 8 * k][tx] = xb[(size_t)(c0 + ty + 8 * k) * HW + n0 + tx];
    __syncthreads();
    bf16* Xh = g_xth + (size_t)b * HW * CH;
    bf16* Xl = g_xtl + (size_t)b * HW * CH;
    #pragma unroll
    for (int k = 0; k < 4; k++) {
        float v = t[tx][ty + 8 * k];
        bf16 h, l; split2(v, h, l);
        size_t off = (size_t)(n0 + ty + 8 * k) * CH + c0 + tx;
        Xh[off] = h; Xl[off] = l;
    }
}

// K0b: split Wq,Wk,Wv into g_wh/g_wl
__global__ __launch_bounds__(256) void k_split_w(
    const float* __restrict__ Wq, const float* __restrict__ Wk, const float* __restrict__ Wv)
{
    int idx = blockIdx.x * 256 + threadIdx.x;
    int p = blockIdx.y;
    const float* W = (p == 0) ? Wq : ((p == 1) ? Wk : Wv);
    float v = W[idx];
    bf16 h, l; split2(v, h, l);
    g_wh[p * AD * CH + idx] = h;
    g_wl[p * AD * CH + idx] = l;
}

// ---------------------------------------------------------------------------
// K1: projections via split MMA (256 thr, 64x32 warp tiles, K32 2-deep).
// ---------------------------------------------------------------------------
__global__ __launch_bounds__(256) void k_proj_mma(
    const float* __restrict__ bq, const float* __restrict__ bk, const float* __restrict__ bv)
{
    MMA_PROLOG();
    int z = blockIdx.z;
    int b = z / 3, p = z % 3;
    int n0 = blockIdx.x * 128;
    int a0 = blockIdx.y * 128;

    const bf16* Ah = g_xth + ((size_t)b * HW + n0) * CH;
    const bf16* Al = g_xtl + ((size_t)b * HW + n0) * CH;
    const bf16* Bh = g_wh + (size_t)p * AD * CH + (size_t)a0 * CH;
    const bf16* Bl = g_wl + (size_t)p * AD * CH + (size_t)a0 * CH;
    const float* bias = (p == 0) ? bq : ((p == 1) ? bk : bv);

    stage_load32(sb, 0, Ah, Al, Bh, Bl, CH, CH, 0, tid);
    const int KS = CH / 32;
    for (int s = 0; s < KS; s++) {
        cp_wait0();
        __syncthreads();
        if (s + 1 < KS)
            stage_load32(sb, (s + 1) & 1, Ah, Al, Bh, Bl, CH, CH, (s + 1) * 32, tid);
        stage_mma32(sb + (s & 1) * STAGE_B, acc, wm, wn, lane);
    }

    __syncthreads();   // mainloop smem dead; reuse as bounce buffer

    if (p < 2) {
        bf16* th = reinterpret_cast<bf16*>(smc);      // [128][136]
        bf16* tl = th + 128 * 136;
        #pragma unroll
        for (int j = 0; j < 4; j++) {
            int c2 = wn * 32 + j * 8 + tg * 2;
            float bb0 = bias[a0 + c2], bb1 = bias[a0 + c2 + 1];
            #pragma unroll
            for (int i = 0; i < 4; i++) {
                int nr = wm * 64 + i * 16 + g;
                #pragma unroll
                for (int half = 0; half < 2; half++) {
                    int nn = nr + half * 8;
                    float v0 = acc[i][j][half * 2 + 0] + bb0;
                    float v1 = acc[i][j][half * 2 + 1] + bb1;
                    bf16 h0, l0, h1, l1;
                    split2(v0, h0, l0); split2(v1, h1, l1);
                    __nv_bfloat162 hh; hh.x = h0; hh.y = h1;
                    __nv_bfloat162 ll; ll.x = l0; ll.y = l1;
                    *reinterpret_cast<__nv_bfloat162*>(&th[nn * 136 + c2]) = hh;
                    *reinterpret_cast<__nv_bfloat162*>(&tl[nn * 136 + c2]) = ll;
                }
            }
        }
        __syncthreads();
        bf16* Yh = ((p == 0) ? g_qh : g_kh) + (size_t)b * HW * AD;
        bf16* Yl = ((p == 0) ? g_ql : g_kl) + (size_t)b * HW * AD;
        int r = tid >> 1, part = tid & 1;
        size_t off = (size_t)(n0 + r) * AD + a0 + part * 64;
        const float4* sh4 = reinterpret_cast<const float4*>(th + r * 136 + part * 64);
        const float4* sl4 = reinterpret_cast<const float4*>(tl + r * 136 + part * 64);
        float4* dh4 = reinterpret_cast<float4*>(Yh + off);
        float4* dl4 = reinterpret_cast<float4*>(Yl + off);
        #pragma unroll
        for (int u = 0; u < 8; u++) { dh4[u] = sh4[u]; dl4[u] = sl4[u]; }
    } else {
        __half* th = reinterpret_cast<__half*>(smc);  // [128][136] transposed
        #pragma unroll
        for (int j = 0; j < 4; j++) {
            int c2 = wn * 32 + j * 8 + tg * 2;
            float bb0 = bias[a0 + c2], bb1 = bias[a0 + c2 + 1];
            #pragma unroll
            for (int i = 0; i < 4; i++) {
                int nr = wm * 64 + i * 16 + g;
                #pragma unroll
                for (int half = 0; half < 2; half++) {
                    int nn = nr + half * 8;
                    th[(c2 + 0) * 136 + nn] = __float2half_rn(acc[i][j][half * 2 + 0] + bb0);
                    th[(c2 + 1) * 136 + nn] = __float2half_rn(acc[i][j][half * 2 + 1] + bb1);
                }
            }
        }
        __syncthreads();
        __half* Tv = g_vt16 + (size_t)b * CH * HW;
        int r = tid >> 1, part = tid & 1;
        size_t off = (size_t)(a0 + r) * HW + n0 + part * 64;
        const float4* sh4 = reinterpret_cast<const float4*>(th + r * 136 + part * 64);
        float4* dh4 = reinterpret_cast<float4*>(Tv + off);
        #pragma unroll
        for (int u = 0; u < 8; u++) dh4[u] = sh4[u];
    }
}

// ---------------------------------------------------------------------------
// K2: S = Q K^T (bf16 split, 3 products) + fused per-tile column stats.
// K=512 as 32 stages of 16, 4-deep cp.async pipeline (wait_group 2).
// ---------------------------------------------------------------------------
__global__ __launch_bounds__(256, 2) void k_scores_mma()
{
    MMA_PROLOG();
    int b = blockIdx.z;
    int m0 = blockIdx.x * 128;   // key block (cols)
    int n0 = blockIdx.y * 128;   // query block (rows)

    const bf16* Ah = g_qh + ((size_t)b * HW + n0) * AD;
    const bf16* Al = g_ql + ((size_t)b * HW + n0) * AD;
    const bf16* Bh = g_kh + ((size_t)b * HW + m0) * AD;
    const bf16* Bl = g_kl + ((size_t)b * HW + m0) * AD;

    stage_load16s(sb, 0, Ah, Al, Bh, Bl, AD, AD, 0, tid);
    stage_load16s(sb, 1, Ah, Al, Bh, Bl, AD, AD, 16, tid);
    stage_load16s(sb, 2, Ah, Al, Bh, Bl, AD, AD, 32, tid);
    const int KS = AD / 16;   // 32
    for (int s = 0; s < KS; s++) {
        cp_wait2();
        __syncthreads();
        if (s + 3 < KS)
            stage_load16s(sb, (s + 3) & 3, Ah, Al, Bh, Bl, AD, AD, (s + 3) * 16, tid);
        else
            cp_commit();
        stage_mma16s(sb + (s & 3) * SC_STAGE_B, acc, wm, wn, lane);
    }

    float* Sb = g_S + (size_t)b * HW * HW;
    #pragma unroll
    for (int i = 0; i < 4; i++) {
        int n = n0 + wm * 64 + i * 16 + g;
        #pragma unroll
        for (int j = 0; j < 4; j++) {
            int m = m0 + wn * 32 + j * 8 + tg * 2;
            *reinterpret_cast<float2*>(&Sb[(size_t)n * HW + m]) =
                make_float2(acc[i][j][0], acc[i][j][1]);
            *reinterpret_cast<float2*>(&Sb[(size_t)(n + 8) * HW + m]) =
                make_float2(acc[i][j][2], acc[i][j][3]);
        }
    }

    // ---- fused column stats over this tile's 128 n-rows ----
    __syncthreads();   // mainloop/LDS fully done; reuse smem
    float* wmax = reinterpret_cast<float*>(smc);   // [2][128]
    float* wsum = wmax + 256;                      // [2][128]

    float cm[8];
    #pragma unroll
    for (int j = 0; j < 4; j++)
        #pragma unroll
        for (int p = 0; p < 2; p++) {
            float mv = -3.4e38f;
            #pragma unroll
            for (int i = 0; i < 4; i++) {
                mv = fmaxf(mv, acc[i][j][p]);
                mv = fmaxf(mv, acc[i][j][2 + p]);
            }
            cm[j * 2 + p] = mv;
        }
    #pragma unroll
    for (int idx = 0; idx < 8; idx++) {
        cm[idx] = fmaxf(cm[idx], __shfl_xor_sync(0xffffffffu, cm[idx], 4));
        cm[idx] = fmaxf(cm[idx], __shfl_xor_sync(0xffffffffu, cm[idx], 8));
        cm[idx] = fmaxf(cm[idx], __shfl_xor_sync(0xffffffffu, cm[idx], 16));
    }
    if (lane < 4) {
        #pragma unroll
        for (int j = 0; j < 4; j++)
            #pragma unroll
            for (int p = 0; p < 2; p++)
                wmax[wm * 128 + wn * 32 + j * 8 + tg * 2 + p] = cm[j * 2 + p];
    }
    __syncthreads();

    float cs[8];
    #pragma unroll
    for (int j = 0; j < 4; j++)
        #pragma unroll
        for (int p = 0; p < 2; p++) {
            int c = wn * 32 + j * 8 + tg * 2 + p;
            float M = fmaxf(wmax[c], wmax[128 + c]);
            float s_ = 0.f;
            #pragma unroll
            for (int i = 0; i < 4; i++) {
                s_ += fast_exp_neg(acc[i][j][p] - M);
                s_ += fast_exp_neg(acc[i][j][2 + p] - M);
            }
            cs[j * 2 + p] = s_;
        }
    #pragma unroll
    for (int idx = 0; idx < 8; idx++) {
        cs[idx] += __shfl_xor_sync(0xffffffffu, cs[idx], 4);
        cs[idx] += __shfl_xor_sync(0xffffffffu, cs[idx], 8);
        cs[idx] += __shfl_xor_sync(0xffffffffu, cs[idx], 16);
    }
    if (lane < 4) {
        #pragma unroll
        for (int j = 0; j < 4; j++)
            #pragma unroll
            for (int p = 0; p < 2; p++)
                wsum[wm * 128 + wn * 32 + j * 8 + tg * 2 + p] = cs[j * 2 + p];
    }
    __syncthreads();

    if (tid < 128) {
        int c = tid;
        float M = fmaxf(wmax[c], wmax[128 + c]);
        float S_ = wsum[c] + wsum[128 + c];
        size_t si = ((size_t)b * 32 + (n0 >> 7)) * HW + m0 + c;
        g_cmax[si] = M;
        g_csum[si] = S_;
    }
}

// ---------------------------------------------------------------------------
// K3: column softmax (axis=-2). Merges precomputed tile stats, then a single
// S-read pass writing P fp16.
// ---------------------------------------------------------------------------
__global__ __launch_bounds__(256) void k_softmax()
{
    int b = blockIdx.y;
    int col = threadIdx.x & 63;
    int m = blockIdx.x * 64 + col;
    int rq = threadIdx.x >> 6;
    const float* Sb = g_S + (size_t)b * HW * HW;
    __half* Pb = g_p16 + (size_t)b * HW * HW;

    float mx = -3.4e38f, den = 0.f;
    #pragma unroll
    for (int t = 0; t < 8; t++) {
        int tn = rq * 8 + t;
        size_t si = ((size_t)b * 32 + tn) * HW + m;
        float m2 = g_cmax[si];
        float d2 = g_csum[si];
        float nm = fmaxf(mx, m2);
        den = den * fast_exp_neg(mx - nm) + d2 * fast_exp_neg(m2 - nm);
        mx = nm;
    }

    __shared__ float smx[256], sden[256];
    __shared__ float cmx[64], cinv[64];
    smx[threadIdx.x] = mx; sden[threadIdx.x] = den;
    __syncthreads();
    if (threadIdx.x < 64) {
        float M = smx[threadIdx.x], D = sden[threadIdx.x];
        #pragma unroll
        for (int k = 1; k < 4; k++) {
            float m2 = smx[threadIdx.x + 64 * k], d2 = sden[threadIdx.x + 64 * k];
            float nm = fmaxf(M, m2);
            D = D * fast_exp_neg(M - nm) + d2 * fast_exp_neg(m2 - nm);
            M = nm;
        }
        cmx[threadIdx.x] = M;
        cinv[threadIdx.x] = 1.0f / D;
    }
    __syncthreads();
    float M = cmx[col], inv = cinv[col];

    int nbeg = rq * (HW / 4), nend = nbeg + (HW / 4);
    for (int n = nbeg; n < nend; n += 8) {
        float v[8];
        #pragma unroll
        for (int u = 0; u < 8; u++) v[u] = Sb[(size_t)(n + u) * HW + m];
        #pragma unroll
        for (int u = 0; u < 8; u++)
            Pb[(size_t)(n + u) * HW + m] = __float2half_rn(fast_exp_neg(v[u] - M) * inv);
    }
}

// ---------------------------------------------------------------------------
// K4: O = P V (fp16 single product) + residual. K=4096, 64 stages of 64,
// 3-deep cp.async pipeline (wait_group 1).
// ---------------------------------------------------------------------------
__global__ __launch_bounds__(256) void k_out_mma(
    const float* __restrict__ x, float* __restrict__ out)
{
    MMA_PROLOG();
    int b = blockIdx.z;
    int c0 = blockIdx.x * 128;
    int n0 = blockIdx.y * 128;

    const __half* A = g_p16 + (size_t)b * HW * HW + (size_t)n0 * HW;
    const __half* B = g_vt16 + ((size_t)b * CH + c0) * HW;

    stage_load_o64(sb, 0, A, B, HW, HW, 0, tid);
    stage_load_o64(sb, 1, A, B, HW, HW, 64, tid);
    const int KS = HW / 64;
    for (int s = 0; s < KS; s++) {
        cp_wait1();
        __syncthreads();
        if (s + 2 < KS)
            stage_load_o64(sb, (s + 2) % 3, A, B, HW, HW, (s + 2) * 64, tid);
        else
            cp_commit();
        stage_mma_o64(sb + (s % 3) * OT_STAGE_B, acc, wm, wn, lane);
    }

    const float* xb = x + (size_t)b * CH * HW;
    float* ob = out + (size_t)b * CH * HW;
    #pragma unroll
    for (int i = 0; i < 4; i++) {
        int n = n0 + wm * 64 + i * 16 + g;
        #pragma unroll
        for (int j = 0; j < 4; j++) {
            int c = c0 + wn * 32 + j * 8 + tg * 2;
            {
                size_t off = (size_t)n * CH + c;
                float2 xv = *reinterpret_cast<const float2*>(&xb[off]);
                *reinterpret_cast<float2*>(&ob[off]) =
                    make_float2(fmaf(0.1f, acc[i][j][0], xv.x),
                                fmaf(0.1f, acc[i][j][1], xv.y));
            }
            {
                size_t off = (size_t)(n + 8) * CH + c;
                float2 xv = *reinterpret_cast<const float2*>(&xb[off]);
                *reinterpret_cast<float2*>(&ob[off]) =
                    make_float2(fmaf(0.1f, acc[i][j][2], xv.x),
                                fmaf(0.1f, acc[i][j][3], xv.y));
            }
        }
    }
}

// ---------------------------------------------------------------------------
extern "C" void kernel_launch(void* const* d_in, const int* in_sizes, int n_in,
                              void* d_out, int out_size)
{
    const float* x  = (const float*)d_in[0];
    const float* Wq = (const float*)d_in[1];
    const float* bq = (const float*)d_in[2];
    const float* Wk = (const float*)d_in[3];
    const float* bk = (const float*)d_in[4];
    const float* Wv = (const float*)d_in[5];
    const float* bv = (const float*)d_in[6];
    float* out = (float*)d_out;

    static int configured = 0;
    if (!configured) {
        cudaFuncSetAttribute(k_proj_mma,   cudaFuncAttributeMaxDynamicSharedMemorySize, SMEM_GEMM);
        cudaFuncSetAttribute(k_scores_mma, cudaFuncAttributeMaxDynamicSharedMemorySize, SC_SMEM);
        cudaFuncSetAttribute(k_out_mma,    cudaFuncAttributeMaxDynamicSharedMemorySize, OT_SMEM);
        configured = 1;
    }

    k_split_x   <<<dim3(HW / 32, CH / 32, BATCH), 256>>>(x);
    k_split_w   <<<dim3(AD * CH / 256, 3), 256>>>(Wq, Wk, Wv);
    k_proj_mma  <<<dim3(HW / 128, AD / 128, BATCH * 3), 256, SMEM_GEMM>>>(bq, bk, bv);
    k_scores_mma<<<dim3(HW / 128, HW / 128, BATCH), 256, SC_SMEM>>>();
    k_softmax   <<<dim3(HW / 64, BATCH), 256>>>();
    k_out_mma   <<<dim3(CH / 128, HW / 128, BATCH), 256, OT_SMEM>>>(x, out);
}

// round 14
// speedup vs baseline: 1.0395x; 1.0395x over previous
#include <cuda_runtime.h>
#include <cuda_bf16.h>
#include <cuda_fp16.h>
#include <cstdint>

#define BATCH 4
#define CH    512
#define HW    4096
#define AD    512

typedef __nv_bfloat16 bf16;

// ---------------- scratch (__device__ globals; no allocation) ---------------
__device__ bf16 g_xth[BATCH * HW * CH];          // x^T [b][n][c] hi
__device__ bf16 g_xtl[BATCH * HW * CH];          // lo
__device__ bf16 g_wh[3 * AD * CH];               // Wq,Wk,Wv hi
__device__ bf16 g_wl[3 * AD * CH];               // lo
__device__ bf16 g_qh[BATCH * HW * AD];
__device__ bf16 g_ql[BATCH * HW * AD];
__device__ bf16 g_kh[BATCH * HW * AD];
__device__ bf16 g_kl[BATCH * HW * AD];
__device__ __half g_vt16[BATCH * CH * HW];       // v^T [b][c][n], fp16
__device__ __half g_p16[(size_t)BATCH * HW * HW]; // tile-normalized probs fp16
__device__ float g_cmax[BATCH * 32 * HW];        // per-row-tile column max
__device__ float g_csum[BATCH * 32 * HW];        // per-row-tile column sumexp

// ---------------- helpers ----------------------------------------------------
__device__ __forceinline__ uint32_t smem_u32(const void* p) {
    uint32_t a;
    asm("{ .reg .u64 t; cvta.to.shared.u64 t, %1; cvt.u32.u64 %0, t; }" : "=r"(a) : "l"(p));
    return a;
}
__device__ __forceinline__ void cp16(uint32_t d, const void* s) {
    asm volatile("cp.async.ca.shared.global [%0], [%1], 16;" :: "r"(d), "l"(s));
}
__device__ __forceinline__ void cp_commit() { asm volatile("cp.async.commit_group;" ::: "memory"); }
__device__ __forceinline__ void cp_wait0()  { asm volatile("cp.async.wait_group 0;" ::: "memory"); }
__device__ __forceinline__ void cp_wait1()  { asm volatile("cp.async.wait_group 1;" ::: "memory"); }

__device__ __forceinline__ void ldsm4(uint32_t* r, uint32_t addr) {
    asm volatile("ldmatrix.sync.aligned.m8n8.x4.shared.b16 {%0,%1,%2,%3}, [%4];"
        : "=r"(r[0]), "=r"(r[1]), "=r"(r[2]), "=r"(r[3]) : "r"(addr));
}

__device__ __forceinline__ void mma16816(float* c,
    uint32_t a0, uint32_t a1, uint32_t a2, uint32_t a3, uint32_t b0, uint32_t b1)
{
    asm volatile(
        "mma.sync.aligned.m16n8k16.row.col.f32.bf16.bf16.f32 "
        "{%0,%1,%2,%3},{%4,%5,%6,%7},{%8,%9},{%0,%1,%2,%3};"
        : "+f"(c[0]), "+f"(c[1]), "+f"(c[2]), "+f"(c[3])
        : "r"(a0), "r"(a1), "r"(a2), "r"(a3), "r"(b0), "r"(b1));
}
__device__ __forceinline__ void mma16816h(float* c,
    uint32_t a0, uint32_t a1, uint32_t a2, uint32_t a3, uint32_t b0, uint32_t b1)
{
    asm volatile(
        "mma.sync.aligned.m16n8k16.row.col.f32.f16.f16.f32 "
        "{%0,%1,%2,%3},{%4,%5,%6,%7},{%8,%9},{%0,%1,%2,%3};"
        : "+f"(c[0]), "+f"(c[1]), "+f"(c[2]), "+f"(c[3])
        : "r"(a0), "r"(a1), "r"(a2), "r"(a3), "r"(b0), "r"(b1));
}

// FMA-only exp (x <= 0)
__device__ __forceinline__ float fast_exp_neg(float x) {
    float t = x * 1.4426950408889634f;
    t = fmaxf(t, -126.0f);
    float r = rintf(t);
    float f = t - r;
    float p = 1.3333558e-3f;
    p = fmaf(p, f, 9.6181291e-3f);
    p = fmaf(p, f, 5.5504110e-2f);
    p = fmaf(p, f, 2.4022651e-1f);
    p = fmaf(p, f, 6.9314718e-1f);
    p = fmaf(p, f, 1.0f);
    return __int_as_float(__float_as_int(p) + ((int)r << 23));
}

__device__ __forceinline__ void split2(float v, bf16& h, bf16& l) {
    h = __float2bfloat16(v);
    l = __float2bfloat16(v - __bfloat162float(h));
}

// ---------------- split-GEMM smem layout: K=32 stages, double-buffered -------
#define TT      40
#define TILE_B  10240
#define STAGE_B 40960
#define SMEM_GEMM (2 * STAGE_B)   // 81920

__device__ __forceinline__ void stage_load32(uint32_t sb, int st,
    const bf16* __restrict__ Ah, const bf16* __restrict__ Al,
    const bf16* __restrict__ Bh, const bf16* __restrict__ Bl,
    int ldA, int ldB, int k0, int tid)
{
    int row = tid >> 1;
    int h0  = (tid & 1) * 16;
    uint32_t d = sb + st * STAGE_B + row * 80 + h0 * 2;
    const size_t oA = (size_t)row * ldA + k0 + h0;
    const size_t oB = (size_t)row * ldB + k0 + h0;
    cp16(d + 0 * TILE_B,      Ah + oA); cp16(d + 0 * TILE_B + 16, Ah + oA + 8);
    cp16(d + 1 * TILE_B,      Al + oA); cp16(d + 1 * TILE_B + 16, Al + oA + 8);
    cp16(d + 2 * TILE_B,      Bh + oB); cp16(d + 2 * TILE_B + 16, Bh + oB + 8);
    cp16(d + 3 * TILE_B,      Bl + oB); cp16(d + 3 * TILE_B + 16, Bl + oB + 8);
    cp_commit();
}

__device__ __forceinline__ void stage_mma32(uint32_t sst, float acc[4][4][4],
                                            int wm, int wn, int lane)
{
    int lane8 = lane & 7, seg = lane >> 3;
    int arow = (seg & 1) << 3, acol = (seg >> 1) << 3;
    int brow = (seg >> 1) << 3, bcol = (seg & 1) << 3;

    #pragma unroll
    for (int kh = 0; kh < 2; kh++) {
        int ko = kh * 16;
        uint32_t ah[4][4], bh[4][2];
        #pragma unroll
        for (int i = 0; i < 4; i++) {
            int r = wm * 64 + i * 16 + lane8 + arow;
            ldsm4(ah[i], sst + 0 * TILE_B + (uint32_t)(r * TT + ko + acol) * 2);
        }
        #pragma unroll
        for (int jp = 0; jp < 2; jp++) {
            int r = wn * 32 + jp * 16 + lane8 + brow;
            uint32_t t[4];
            ldsm4(t, sst + 2 * TILE_B + (uint32_t)(r * TT + ko + bcol) * 2);
            bh[jp * 2][0] = t[0];     bh[jp * 2][1] = t[1];
            bh[jp * 2 + 1][0] = t[2]; bh[jp * 2 + 1][1] = t[3];
        }
        #pragma unroll
        for (int i = 0; i < 4; i++)
            #pragma unroll
            for (int j = 0; j < 4; j++)
                mma16816(acc[i][j], ah[i][0], ah[i][1], ah[i][2], ah[i][3], bh[j][0], bh[j][1]);

        uint32_t bl[4][2];
        #pragma unroll
        for (int jp = 0; jp < 2; jp++) {
            int r = wn * 32 + jp * 16 + lane8 + brow;
            uint32_t t[4];
            ldsm4(t, sst + 3 * TILE_B + (uint32_t)(r * TT + ko + bcol) * 2);
            bl[jp * 2][0] = t[0];     bl[jp * 2][1] = t[1];
            bl[jp * 2 + 1][0] = t[2]; bl[jp * 2 + 1][1] = t[3];
        }
        #pragma unroll
        for (int i = 0; i < 4; i++)
            #pragma unroll
            for (int j = 0; j < 4; j++)
                mma16816(acc[i][j], ah[i][0], ah[i][1], ah[i][2], ah[i][3], bl[j][0], bl[j][1]);

        uint32_t al[4][4];
        #pragma unroll
        for (int i = 0; i < 4; i++) {
            int r = wm * 64 + i * 16 + lane8 + arow;
            ldsm4(al[i], sst + 1 * TILE_B + (uint32_t)(r * TT + ko + acol) * 2);
        }
        #pragma unroll
        for (int i = 0; i < 4; i++)
            #pragma unroll
            for (int j = 0; j < 4; j++)
                mma16816(acc[i][j], al[i][0], al[i][1], al[i][2], al[i][3], bh[j][0], bh[j][1]);
    }
}

#define MMA_PROLOG()                                                             \
    extern __shared__ char smc[];                                                \
    uint32_t sb = smem_u32(smc);                                                 \
    int tid = threadIdx.x, lane = tid & 31, wid = tid >> 5;                      \
    int wm = wid & 1, wn = wid >> 1, g = lane >> 2, tg = lane & 3;               \
    float acc[4][4][4];                                                          \
    _Pragma("unroll")                                                            \
    for (int i = 0; i < 4; i++)                                                  \
        _Pragma("unroll")                                                        \
        for (int j = 0; j < 4; j++)                                              \
            _Pragma("unroll")                                                    \
            for (int r = 0; r < 4; r++) acc[i][j][r] = 0.f;

#define MMA_MAINLOOP_SPLIT(Ah, Al, Bh, Bl, ldA, ldB, KS)                         \
    stage_load32(sb, 0, Ah, Al, Bh, Bl, ldA, ldB, 0, tid);                       \
    for (int s = 0; s < (KS); s++) {                                             \
        cp_wait0();                                                              \
        __syncthreads();                                                         \
        if (s + 1 < (KS))                                                        \
            stage_load32(sb, (s + 1) & 1, Ah, Al, Bh, Bl, ldA, ldB,              \
                         (s + 1) * 32, tid);                                     \
        stage_mma32(sb + (s & 1) * STAGE_B, acc, wm, wn, lane);                  \
    }

// ---------------- k_out smem layout: fp16, 2 tiles, K=64, 3-deep pipeline ----
#define TTO        72
#define OT_TILE_B  18432
#define OT_STAGE_B 36864
#define OT_SMEM    (3 * OT_STAGE_B)   // 110592 -> 2 CTA/SM

__device__ __forceinline__ void stage_load_o64(uint32_t sb, int st,
    const __half* __restrict__ A, const __half* __restrict__ B,
    int ldA, int ldB, int k0, int tid)
{
    int row = tid >> 1;
    int seg = tid & 1;
    uint32_t d = sb + st * OT_STAGE_B + row * 144 + seg * 64;
    const size_t oA = (size_t)row * ldA + k0 + seg * 32;
    const size_t oB = (size_t)row * ldB + k0 + seg * 32;
    #pragma unroll
    for (int u = 0; u < 4; u++) {
        cp16(d + u * 16,              A + oA + u * 8);
        cp16(d + OT_TILE_B + u * 16,  B + oB + u * 8);
    }
    cp_commit();
}

__device__ __forceinline__ void stage_mma_o64(uint32_t sst, float acc[4][4][4],
                                              int wm, int wn, int lane)
{
    int lane8 = lane & 7, seg = lane >> 3;
    int arow = (seg & 1) << 3, acol = (seg >> 1) << 3;
    int brow = (seg >> 1) << 3, bcol = (seg & 1) << 3;

    #pragma unroll
    for (int kh = 0; kh < 4; kh++) {
        int ko = kh * 16;
        uint32_t a[4][4], b[4][2];
        #pragma unroll
        for (int i = 0; i < 4; i++) {
            int r = wm * 64 + i * 16 + lane8 + arow;
            ldsm4(a[i], sst + (uint32_t)(r * TTO + ko + acol) * 2);
        }
        #pragma unroll
        for (int jp = 0; jp < 2; jp++) {
            int r = wn * 32 + jp * 16 + lane8 + brow;
            uint32_t t[4];
            ldsm4(t, sst + OT_TILE_B + (uint32_t)(r * TTO + ko + bcol) * 2);
            b[jp * 2][0] = t[0];     b[jp * 2][1] = t[1];
            b[jp * 2 + 1][0] = t[2]; b[jp * 2 + 1][1] = t[3];
        }
        #pragma unroll
        for (int i = 0; i < 4; i++)
            #pragma unroll
            for (int j = 0; j < 4; j++)
                mma16816h(acc[i][j], a[i][0], a[i][1], a[i][2], a[i][3], b[j][0], b[j][1]);
    }
}

// ---------------------------------------------------------------------------
// K0a: x [b][c][n] -> transposed split xt hi/lo [b][n][c]
// ---------------------------------------------------------------------------
__global__ __launch_bounds__(256) void k_split_x(const float* __restrict__ x)
{
    __shared__ float t[32][33];
    int b = blockIdx.z;
    int n0 = blockIdx.x * 32, c0 = blockIdx.y * 32;
    int tx = threadIdx.x & 31, ty = threadIdx.x >> 5;

    const float* xb = x + (size_t)b * CH * HW;
    #pragma unroll
    for (int k = 0; k < 4; k++)
        t[ty + 8 * k][tx] = xb[(size_t)(c0 + ty + 8 * k) * HW + n0 + tx];
    __syncthreads();
    bf16* Xh = g_xth + (size_t)b * HW * CH;
    bf16* Xl = g_xtl + (size_t)b * HW * CH;
    #pragma unroll
    for (int k = 0; k < 4; k++) {
        float v = t[tx][ty + 8 * k];
        bf16 h, l; split2(v, h, l);
        size_t off = (size_t)(n0 + ty + 8 * k) * CH + c0 + tx;
        Xh[off] = h; Xl[off] = l;
    }
}

// K0b: split Wq,Wk,Wv into g_wh/g_wl
__global__ __launch_bounds__(256) void k_split_w(
    const float* __restrict__ Wq, const float* __restrict__ Wk, const float* __restrict__ Wv)
{
    int idx = blockIdx.x * 256 + threadIdx.x;
    int p = blockIdx.y;
    const float* W = (p == 0) ? Wq : ((p == 1) ? Wk : Wv);
    float v = W[idx];
    bf16 h, l; split2(v, h, l);
    g_wh[p * AD * CH + idx] = h;
    g_wl[p * AD * CH + idx] = l;
}

// ---------------------------------------------------------------------------
// K1: projections via split MMA (256 thr, 64x32 warp tiles, K32 2-deep).
// ---------------------------------------------------------------------------
__global__ __launch_bounds__(256) void k_proj_mma(
    const float* __restrict__ bq, const float* __restrict__ bk, const float* __restrict__ bv)
{
    MMA_PROLOG();
    int z = blockIdx.z;
    int b = z / 3, p = z % 3;
    int n0 = blockIdx.x * 128;
    int a0 = blockIdx.y * 128;

    const bf16* Ah = g_xth + ((size_t)b * HW + n0) * CH;
    const bf16* Al = g_xtl + ((size_t)b * HW + n0) * CH;
    const bf16* Bh = g_wh + (size_t)p * AD * CH + (size_t)a0 * CH;
    const bf16* Bl = g_wl + (size_t)p * AD * CH + (size_t)a0 * CH;
    const float* bias = (p == 0) ? bq : ((p == 1) ? bk : bv);

    MMA_MAINLOOP_SPLIT(Ah, Al, Bh, Bl, CH, CH, CH / 32);

    __syncthreads();   // mainloop smem dead; reuse as bounce buffer

    if (p < 2) {
        bf16* th = reinterpret_cast<bf16*>(smc);      // [128][136]
        bf16* tl = th + 128 * 136;
        #pragma unroll
        for (int j = 0; j < 4; j++) {
            int c2 = wn * 32 + j * 8 + tg * 2;
            float bb0 = bias[a0 + c2], bb1 = bias[a0 + c2 + 1];
            #pragma unroll
            for (int i = 0; i < 4; i++) {
                int nr = wm * 64 + i * 16 + g;
                #pragma unroll
                for (int half = 0; half < 2; half++) {
                    int nn = nr + half * 8;
                    float v0 = acc[i][j][half * 2 + 0] + bb0;
                    float v1 = acc[i][j][half * 2 + 1] + bb1;
                    bf16 h0, l0, h1, l1;
                    split2(v0, h0, l0); split2(v1, h1, l1);
                    __nv_bfloat162 hh; hh.x = h0; hh.y = h1;
                    __nv_bfloat162 ll; ll.x = l0; ll.y = l1;
                    *reinterpret_cast<__nv_bfloat162*>(&th[nn * 136 + c2]) = hh;
                    *reinterpret_cast<__nv_bfloat162*>(&tl[nn * 136 + c2]) = ll;
                }
            }
        }
        __syncthreads();
        bf16* Yh = ((p == 0) ? g_qh : g_kh) + (size_t)b * HW * AD;
        bf16* Yl = ((p == 0) ? g_ql : g_kl) + (size_t)b * HW * AD;
        int r = tid >> 1, part = tid & 1;
        size_t off = (size_t)(n0 + r) * AD + a0 + part * 64;
        const float4* sh4 = reinterpret_cast<const float4*>(th + r * 136 + part * 64);
        const float4* sl4 = reinterpret_cast<const float4*>(tl + r * 136 + part * 64);
        float4* dh4 = reinterpret_cast<float4*>(Yh + off);
        float4* dl4 = reinterpret_cast<float4*>(Yl + off);
        #pragma unroll
        for (int u = 0; u < 8; u++) { dh4[u] = sh4[u]; dl4[u] = sl4[u]; }
    } else {
        __half* th = reinterpret_cast<__half*>(smc);  // [128][136] transposed
        #pragma unroll
        for (int j = 0; j < 4; j++) {
            int c2 = wn * 32 + j * 8 + tg * 2;
            float bb0 = bias[a0 + c2], bb1 = bias[a0 + c2 + 1];
            #pragma unroll
            for (int i = 0; i < 4; i++) {
                int nr = wm * 64 + i * 16 + g;
                #pragma unroll
                for (int half = 0; half < 2; half++) {
                    int nn = nr + half * 8;
                    th[(c2 + 0) * 136 + nn] = __float2half_rn(acc[i][j][half * 2 + 0] + bb0);
                    th[(c2 + 1) * 136 + nn] = __float2half_rn(acc[i][j][half * 2 + 1] + bb1);
                }
            }
        }
        __syncthreads();
        __half* Tv = g_vt16 + (size_t)b * CH * HW;
        int r = tid >> 1, part = tid & 1;
        size_t off = (size_t)(a0 + r) * HW + n0 + part * 64;
        const float4* sh4 = reinterpret_cast<const float4*>(th + r * 136 + part * 64);
        float4* dh4 = reinterpret_cast<float4*>(Tv + off);
        #pragma unroll
        for (int u = 0; u < 8; u++) dh4[u] = sh4[u];
    }
}

// ---------------------------------------------------------------------------
// K2: S = Q K^T (bf16 split, 3 products), K32 2-deep (R12 mainloop).
// Epilogue: per-tile column max -> write p_tile = exp(acc - M_tile) fp16
// directly to g_p16, plus per-tile column stats to g_cmax/g_csum.
// ---------------------------------------------------------------------------
__global__ __launch_bounds__(256, 2) void k_scores_mma()
{
    MMA_PROLOG();
    int b = blockIdx.z;
    int m0 = blockIdx.x * 128;   // key block (cols)
    int n0 = blockIdx.y * 128;   // query block (rows)

    const bf16* Ah = g_qh + ((size_t)b * HW + n0) * AD;
    const bf16* Al = g_ql + ((size_t)b * HW + n0) * AD;
    const bf16* Bh = g_kh + ((size_t)b * HW + m0) * AD;
    const bf16* Bl = g_kl + ((size_t)b * HW + m0) * AD;

    MMA_MAINLOOP_SPLIT(Ah, Al, Bh, Bl, AD, AD, AD / 32);

    __syncthreads();   // mainloop smem dead; reuse for stats
    float* wmax = reinterpret_cast<float*>(smc);   // [2][128]
    float* wsum = wmax + 256;                      // [2][128]

    // Phase 1: per-column tile max
    float cm[8];
    #pragma unroll
    for (int j = 0; j < 4; j++)
        #pragma unroll
        for (int p = 0; p < 2; p++) {
            float mv = -3.4e38f;
            #pragma unroll
            for (int i = 0; i < 4; i++) {
                mv = fmaxf(mv, acc[i][j][p]);
                mv = fmaxf(mv, acc[i][j][2 + p]);
            }
            cm[j * 2 + p] = mv;
        }
    #pragma unroll
    for (int idx = 0; idx < 8; idx++) {
        cm[idx] = fmaxf(cm[idx], __shfl_xor_sync(0xffffffffu, cm[idx], 4));
        cm[idx] = fmaxf(cm[idx], __shfl_xor_sync(0xffffffffu, cm[idx], 8));
        cm[idx] = fmaxf(cm[idx], __shfl_xor_sync(0xffffffffu, cm[idx], 16));
    }
    if (lane < 4) {
        #pragma unroll
        for (int j = 0; j < 4; j++)
            #pragma unroll
            for (int p = 0; p < 2; p++)
                wmax[wm * 128 + wn * 32 + j * 8 + tg * 2 + p] = cm[j * 2 + p];
    }
    __syncthreads();

    // Phase 2: exp, write p16, accumulate sums
    __half* Pb = g_p16 + (size_t)b * HW * HW;
    float cs[8];
    #pragma unroll
    for (int j = 0; j < 4; j++)
        #pragma unroll
        for (int p = 0; p < 2; p++) {
            int c = wn * 32 + j * 8 + tg * 2 + p;
            float M = fmaxf(wmax[c], wmax[128 + c]);
            float s_ = 0.f;
            #pragma unroll
            for (int i = 0; i < 4; i++) {
                int n = n0 + wm * 64 + i * 16 + g;
                int m = m0 + c;
                float e0 = fast_exp_neg(acc[i][j][p] - M);
                float e1 = fast_exp_neg(acc[i][j][2 + p] - M);
                s_ += e0 + e1;
                Pb[(size_t)n * HW + m] = __float2half_rn(e0);
                Pb[(size_t)(n + 8) * HW + m] = __float2half_rn(e1);
            }
            cs[j * 2 + p] = s_;
        }
    #pragma unroll
    for (int idx = 0; idx < 8; idx++) {
        cs[idx] += __shfl_xor_sync(0xffffffffu, cs[idx], 4);
        cs[idx] += __shfl_xor_sync(0xffffffffu, cs[idx], 8);
        cs[idx] += __shfl_xor_sync(0xffffffffu, cs[idx], 16);
    }
    if (lane < 4) {
        #pragma unroll
        for (int j = 0; j < 4; j++)
            #pragma unroll
            for (int p = 0; p < 2; p++)
                wsum[wm * 128 + wn * 32 + j * 8 + tg * 2 + p] = cs[j * 2 + p];
    }
    __syncthreads();

    if (tid < 128) {
        int c = tid;
        float M = fmaxf(wmax[c], wmax[128 + c]);
        float S_ = wsum[c] + wsum[128 + c];
        size_t si = ((size_t)b * 32 + (n0 >> 7)) * HW + m0 + c;
        g_cmax[si] = M;
        g_csum[si] = S_;
    }
}

// ---------------------------------------------------------------------------
// K3: column softmax finalize. Merge tile stats -> per-(tile,col) scale
// factor, then in-place rescale of g_p16 (no S buffer, no exp pass).
// ---------------------------------------------------------------------------
__global__ __launch_bounds__(256) void k_softmax()
{
    int b = blockIdx.y;
    int col = threadIdx.x & 63;
    int m = blockIdx.x * 64 + col;
    int rq = threadIdx.x >> 6;
    __half* Pb = g_p16 + (size_t)b * HW * HW;

    // merge 8 tile-stats per thread (32 tiles / 4 rq groups)
    float m2s[8];
    float mx = -3.4e38f, den = 0.f;
    #pragma unroll
    for (int t = 0; t < 8; t++) {
        int tn = rq * 8 + t;
        size_t si = ((size_t)b * 32 + tn) * HW + m;
        float m2 = g_cmax[si];
        float d2 = g_csum[si];
        m2s[t] = m2;
        float nm = fmaxf(mx, m2);
        den = den * fast_exp_neg(mx - nm) + d2 * fast_exp_neg(m2 - nm);
        mx = nm;
    }

    __shared__ float smx[256], sden[256];
    __shared__ float cmx[64], cinv[64];
    smx[threadIdx.x] = mx; sden[threadIdx.x] = den;
    __syncthreads();
    if (threadIdx.x < 64) {
        float M = smx[threadIdx.x], D = sden[threadIdx.x];
        #pragma unroll
        for (int k = 1; k < 4; k++) {
            float m2 = smx[threadIdx.x + 64 * k], d2 = sden[threadIdx.x + 64 * k];
            float nm = fmaxf(M, m2);
            D = D * fast_exp_neg(M - nm) + d2 * fast_exp_neg(m2 - nm);
            M = nm;
        }
        cmx[threadIdx.x] = M;
        cinv[threadIdx.x] = 1.0f / D;
    }
    __syncthreads();
    float M = cmx[col], inv = cinv[col];

    // in-place rescale: P = p_tile * exp(M_tile - M) * inv
    #pragma unroll
    for (int t = 0; t < 8; t++) {
        float fac = fast_exp_neg(m2s[t] - M) * inv;
        int base = (rq * 8 + t) * 128;
        for (int n = base; n < base + 128; n += 8) {
            float v[8];
            #pragma unroll
            for (int u = 0; u < 8; u++)
                v[u] = __half2float(Pb[(size_t)(n + u) * HW + m]);
            #pragma unroll
            for (int u = 0; u < 8; u++)
                Pb[(size_t)(n + u) * HW + m] = __float2half_rn(v[u] * fac);
        }
    }
}

// ---------------------------------------------------------------------------
// K4: O = P V (fp16 single product) + residual. K=4096, 64 stages of 64,
// 3-deep cp.async pipeline (wait_group 1).
// ---------------------------------------------------------------------------
__global__ __launch_bounds__(256) void k_out_mma(
    const float* __restrict__ x, float* __restrict__ out)
{
    MMA_PROLOG();
    int b = blockIdx.z;
    int c0 = blockIdx.x * 128;
    int n0 = blockIdx.y * 128;

    const __half* A = g_p16 + (size_t)b * HW * HW + (size_t)n0 * HW;
    const __half* B = g_vt16 + ((size_t)b * CH + c0) * HW;

    stage_load_o64(sb, 0, A, B, HW, HW, 0, tid);
    stage_load_o64(sb, 1, A, B, HW, HW, 64, tid);
    const int KS = HW / 64;
    for (int s = 0; s < KS; s++) {
        cp_wait1();
        __syncthreads();
        if (s + 2 < KS)
            stage_load_o64(sb, (s + 2) % 3, A, B, HW, HW, (s + 2) * 64, tid);
        else
            cp_commit();
        stage_mma_o64(sb + (s % 3) * OT_STAGE_B, acc, wm, wn, lane);
    }

    const float* xb = x + (size_t)b * CH * HW;
    float* ob = out + (size_t)b * CH * HW;
    #pragma unroll
    for (int i = 0; i < 4; i++) {
        int n = n0 + wm * 64 + i * 16 + g;
        #pragma unroll
        for (int j = 0; j < 4; j++) {
            int c = c0 + wn * 32 + j * 8 + tg * 2;
            {
                size_t off = (size_t)n * CH + c;
                float2 xv = *reinterpret_cast<const float2*>(&xb[off]);
                *reinterpret_cast<float2*>(&ob[off]) =
                    make_float2(fmaf(0.1f, acc[i][j][0], xv.x),
                                fmaf(0.1f, acc[i][j][1], xv.y));
            }
            {
                size_t off = (size_t)(n + 8) * CH + c;
                float2 xv = *reinterpret_cast<const float2*>(&xb[off]);
                *reinterpret_cast<float2*>(&ob[off]) =
                    make_float2(fmaf(0.1f, acc[i][j][2], xv.x),
                                fmaf(0.1f, acc[i][j][3], xv.y));
            }
        }
    }
}

// ---------------------------------------------------------------------------
extern "C" void kernel_launch(void* const* d_in, const int* in_sizes, int n_in,
                              void* d_out, int out_size)
{
    const float* x  = (const float*)d_in[0];
    const float* Wq = (const float*)d_in[1];
    const float* bq = (const float*)d_in[2];
    const float* Wk = (const float*)d_in[3];
    const float* bk = (const float*)d_in[4];
    const float* Wv = (const float*)d_in[5];
    const float* bv = (const float*)d_in[6];
    float* out = (float*)d_out;

    static int configured = 0;
    if (!configured) {
        cudaFuncSetAttribute(k_proj_mma,   cudaFuncAttributeMaxDynamicSharedMemorySize, SMEM_GEMM);
        cudaFuncSetAttribute(k_scores_mma, cudaFuncAttributeMaxDynamicSharedMemorySize, SMEM_GEMM);
        cudaFuncSetAttribute(k_out_mma,    cudaFuncAttributeMaxDynamicSharedMemorySize, OT_SMEM);
        configured = 1;
    }

    k_split_x   <<<dim3(HW / 32, CH / 32, BATCH), 256>>>(x);
    k_split_w   <<<dim3(AD * CH / 256, 3), 256>>>(Wq, Wk, Wv);
    k_proj_mma  <<<dim3(HW / 128, AD / 128, BATCH * 3), 256, SMEM_GEMM>>>(bq, bk, bv);
    k_scores_mma<<<dim3(HW / 128, HW / 128, BATCH), 256, SMEM_GEMM>>>();
    k_softmax   <<<dim3(HW / 64, BATCH), 256>>>();
    k_out_mma   <<<dim3(CH / 128, HW / 128, BATCH), 256, OT_SMEM>>>(x, out);
}

// round 15
// speedup vs baseline: 1.0780x; 1.0371x over previous
#include <cuda_runtime.h>
#include <cuda_bf16.h>
#include <cuda_fp16.h>
#include <cstdint>

#define BATCH 4
#define CH    512
#define HW    4096
#define AD    512

typedef __nv_bfloat16 bf16;

// ---------------- scratch (__device__ globals; no allocation) ---------------
__device__ bf16 g_xth[BATCH * HW * CH];          // x^T [b][n][c] hi
__device__ bf16 g_xtl[BATCH * HW * CH];          // lo
__device__ bf16 g_wh[3 * AD * CH];               // Wq,Wk,Wv hi
__device__ bf16 g_wl[3 * AD * CH];               // lo
__device__ bf16 g_qh[BATCH * HW * AD];
__device__ bf16 g_ql[BATCH * HW * AD];
__device__ bf16 g_kh[BATCH * HW * AD];
__device__ bf16 g_kl[BATCH * HW * AD];
__device__ __half g_vt16[BATCH * CH * HW];       // v^T [b][c][n], fp16
__device__ __half g_p16[(size_t)BATCH * HW * HW]; // tile-normalized probs fp16
__device__ float g_cmax[BATCH * 32 * HW];        // per-row-tile column max
__device__ float g_csum[BATCH * 32 * HW];        // per-row-tile column sumexp

// ---------------- helpers ----------------------------------------------------
__device__ __forceinline__ uint32_t smem_u32(const void* p) {
    uint32_t a;
    asm("{ .reg .u64 t; cvta.to.shared.u64 t, %1; cvt.u32.u64 %0, t; }" : "=r"(a) : "l"(p));
    return a;
}
__device__ __forceinline__ void cp16(uint32_t d, const void* s) {
    asm volatile("cp.async.ca.shared.global [%0], [%1], 16;" :: "r"(d), "l"(s));
}
__device__ __forceinline__ void cp_commit() { asm volatile("cp.async.commit_group;" ::: "memory"); }
__device__ __forceinline__ void cp_wait0()  { asm volatile("cp.async.wait_group 0;" ::: "memory"); }
__device__ __forceinline__ void cp_wait1()  { asm volatile("cp.async.wait_group 1;" ::: "memory"); }

__device__ __forceinline__ void ldsm4(uint32_t* r, uint32_t addr) {
    asm volatile("ldmatrix.sync.aligned.m8n8.x4.shared.b16 {%0,%1,%2,%3}, [%4];"
        : "=r"(r[0]), "=r"(r[1]), "=r"(r[2]), "=r"(r[3]) : "r"(addr));
}

__device__ __forceinline__ void mma16816(float* c,
    uint32_t a0, uint32_t a1, uint32_t a2, uint32_t a3, uint32_t b0, uint32_t b1)
{
    asm volatile(
        "mma.sync.aligned.m16n8k16.row.col.f32.bf16.bf16.f32 "
        "{%0,%1,%2,%3},{%4,%5,%6,%7},{%8,%9},{%0,%1,%2,%3};"
        : "+f"(c[0]), "+f"(c[1]), "+f"(c[2]), "+f"(c[3])
        : "r"(a0), "r"(a1), "r"(a2), "r"(a3), "r"(b0), "r"(b1));
}
__device__ __forceinline__ void mma16816h(float* c,
    uint32_t a0, uint32_t a1, uint32_t a2, uint32_t a3, uint32_t b0, uint32_t b1)
{
    asm volatile(
        "mma.sync.aligned.m16n8k16.row.col.f32.f16.f16.f32 "
        "{%0,%1,%2,%3},{%4,%5,%6,%7},{%8,%9},{%0,%1,%2,%3};"
        : "+f"(c[0]), "+f"(c[1]), "+f"(c[2]), "+f"(c[3])
        : "r"(a0), "r"(a1), "r"(a2), "r"(a3), "r"(b0), "r"(b1));
}

// FMA-only exp (x <= 0)
__device__ __forceinline__ float fast_exp_neg(float x) {
    float t = x * 1.4426950408889634f;
    t = fmaxf(t, -126.0f);
    float r = rintf(t);
    float f = t - r;
    float p = 1.3333558e-3f;
    p = fmaf(p, f, 9.6181291e-3f);
    p = fmaf(p, f, 5.5504110e-2f);
    p = fmaf(p, f, 2.4022651e-1f);
    p = fmaf(p, f, 6.9314718e-1f);
    p = fmaf(p, f, 1.0f);
    return __int_as_float(__float_as_int(p) + ((int)r << 23));
}

__device__ __forceinline__ void split2(float v, bf16& h, bf16& l) {
    h = __float2bfloat16(v);
    l = __float2bfloat16(v - __bfloat162float(h));
}

// ---------------- split-GEMM smem layout: K=32 stages, double-buffered -------
#define TT      40
#define TILE_B  10240
#define STAGE_B 40960
#define SMEM_GEMM (2 * STAGE_B)   // 81920

__device__ __forceinline__ void stage_load32(uint32_t sb, int st,
    const bf16* __restrict__ Ah, const bf16* __restrict__ Al,
    const bf16* __restrict__ Bh, const bf16* __restrict__ Bl,
    int ldA, int ldB, int k0, int tid)
{
    int row = tid >> 1;
    int h0  = (tid & 1) * 16;
    uint32_t d = sb + st * STAGE_B + row * 80 + h0 * 2;
    const size_t oA = (size_t)row * ldA + k0 + h0;
    const size_t oB = (size_t)row * ldB + k0 + h0;
    cp16(d + 0 * TILE_B,      Ah + oA); cp16(d + 0 * TILE_B + 16, Ah + oA + 8);
    cp16(d + 1 * TILE_B,      Al + oA); cp16(d + 1 * TILE_B + 16, Al + oA + 8);
    cp16(d + 2 * TILE_B,      Bh + oB); cp16(d + 2 * TILE_B + 16, Bh + oB + 8);
    cp16(d + 3 * TILE_B,      Bl + oB); cp16(d + 3 * TILE_B + 16, Bl + oB + 8);
    cp_commit();
}

__device__ __forceinline__ void stage_mma32(uint32_t sst, float acc[4][4][4],
                                            int wm, int wn, int lane)
{
    int lane8 = lane & 7, seg = lane >> 3;
    int arow = (seg & 1) << 3, acol = (seg >> 1) << 3;
    int brow = (seg >> 1) << 3, bcol = (seg & 1) << 3;

    #pragma unroll
    for (int kh = 0; kh < 2; kh++) {
        int ko = kh * 16;
        uint32_t ah[4][4], bh[4][2];
        #pragma unroll
        for (int i = 0; i < 4; i++) {
            int r = wm * 64 + i * 16 + lane8 + arow;
            ldsm4(ah[i], sst + 0 * TILE_B + (uint32_t)(r * TT + ko + acol) * 2);
        }
        #pragma unroll
        for (int jp = 0; jp < 2; jp++) {
            int r = wn * 32 + jp * 16 + lane8 + brow;
            uint32_t t[4];
            ldsm4(t, sst + 2 * TILE_B + (uint32_t)(r * TT + ko + bcol) * 2);
            bh[jp * 2][0] = t[0];     bh[jp * 2][1] = t[1];
            bh[jp * 2 + 1][0] = t[2]; bh[jp * 2 + 1][1] = t[3];
        }
        #pragma unroll
        for (int i = 0; i < 4; i++)
            #pragma unroll
            for (int j = 0; j < 4; j++)
                mma16816(acc[i][j], ah[i][0], ah[i][1], ah[i][2], ah[i][3], bh[j][0], bh[j][1]);

        uint32_t bl[4][2];
        #pragma unroll
        for (int jp = 0; jp < 2; jp++) {
            int r = wn * 32 + jp * 16 + lane8 + brow;
            uint32_t t[4];
            ldsm4(t, sst + 3 * TILE_B + (uint32_t)(r * TT + ko + bcol) * 2);
            bl[jp * 2][0] = t[0];     bl[jp * 2][1] = t[1];
            bl[jp * 2 + 1][0] = t[2]; bl[jp * 2 + 1][1] = t[3];
        }
        #pragma unroll
        for (int i = 0; i < 4; i++)
            #pragma unroll
            for (int j = 0; j < 4; j++)
                mma16816(acc[i][j], ah[i][0], ah[i][1], ah[i][2], ah[i][3], bl[j][0], bl[j][1]);

        uint32_t al[4][4];
        #pragma unroll
        for (int i = 0; i < 4; i++) {
            int r = wm * 64 + i * 16 + lane8 + arow;
            ldsm4(al[i], sst + 1 * TILE_B + (uint32_t)(r * TT + ko + acol) * 2);
        }
        #pragma unroll
        for (int i = 0; i < 4; i++)
            #pragma unroll
            for (int j = 0; j < 4; j++)
                mma16816(acc[i][j], al[i][0], al[i][1], al[i][2], al[i][3], bh[j][0], bh[j][1]);
    }
}

#define MMA_PROLOG()                                                             \
    extern __shared__ char smc[];                                                \
    uint32_t sb = smem_u32(smc);                                                 \
    int tid = threadIdx.x, lane = tid & 31, wid = tid >> 5;                      \
    int wm = wid & 1, wn = wid >> 1, g = lane >> 2, tg = lane & 3;               \
    float acc[4][4][4];                                                          \
    _Pragma("unroll")                                                            \
    for (int i = 0; i < 4; i++)                                                  \
        _Pragma("unroll")                                                        \
        for (int j = 0; j < 4; j++)                                              \
            _Pragma("unroll")                                                    \
            for (int r = 0; r < 4; r++) acc[i][j][r] = 0.f;

#define MMA_MAINLOOP_SPLIT(Ah, Al, Bh, Bl, ldA, ldB, KS)                         \
    stage_load32(sb, 0, Ah, Al, Bh, Bl, ldA, ldB, 0, tid);                       \
    for (int s = 0; s < (KS); s++) {                                             \
        cp_wait0();                                                              \
        __syncthreads();                                                         \
        if (s + 1 < (KS))                                                        \
            stage_load32(sb, (s + 1) & 1, Ah, Al, Bh, Bl, ldA, ldB,              \
                         (s + 1) * 32, tid);                                     \
        stage_mma32(sb + (s & 1) * STAGE_B, acc, wm, wn, lane);                  \
    }

// ---------------- k_out smem layout: fp16, 2 tiles, K=64, 3-deep pipeline ----
#define TTO        72
#define OT_TILE_B  18432
#define OT_STAGE_B 36864
#define OT_SMEM    (3 * OT_STAGE_B)   // 110592 -> 2 CTA/SM

__device__ __forceinline__ void stage_load_o64(uint32_t sb, int st,
    const __half* __restrict__ A, const __half* __restrict__ B,
    int ldA, int ldB, int k0, int tid)
{
    int row = tid >> 1;
    int seg = tid & 1;
    uint32_t d = sb + st * OT_STAGE_B + row * 144 + seg * 64;
    const size_t oA = (size_t)row * ldA + k0 + seg * 32;
    const size_t oB = (size_t)row * ldB + k0 + seg * 32;
    #pragma unroll
    for (int u = 0; u < 4; u++) {
        cp16(d + u * 16,              A + oA + u * 8);
        cp16(d + OT_TILE_B + u * 16,  B + oB + u * 8);
    }
    cp_commit();
}

__device__ __forceinline__ void stage_mma_o64(uint32_t sst, float acc[4][4][4],
                                              int wm, int wn, int lane)
{
    int lane8 = lane & 7, seg = lane >> 3;
    int arow = (seg & 1) << 3, acol = (seg >> 1) << 3;
    int brow = (seg >> 1) << 3, bcol = (seg & 1) << 3;

    #pragma unroll
    for (int kh = 0; kh < 4; kh++) {
        int ko = kh * 16;
        uint32_t a[4][4], b[4][2];
        #pragma unroll
        for (int i = 0; i < 4; i++) {
            int r = wm * 64 + i * 16 + lane8 + arow;
            ldsm4(a[i], sst + (uint32_t)(r * TTO + ko + acol) * 2);
        }
        #pragma unroll
        for (int jp = 0; jp < 2; jp++) {
            int r = wn * 32 + jp * 16 + lane8 + brow;
            uint32_t t[4];
            ldsm4(t, sst + OT_TILE_B + (uint32_t)(r * TTO + ko + bcol) * 2);
            b[jp * 2][0] = t[0];     b[jp * 2][1] = t[1];
            b[jp * 2 + 1][0] = t[2]; b[jp * 2 + 1][1] = t[3];
        }
        #pragma unroll
        for (int i = 0; i < 4; i++)
            #pragma unroll
            for (int j = 0; j < 4; j++)
                mma16816h(acc[i][j], a[i][0], a[i][1], a[i][2], a[i][3], b[j][0], b[j][1]);
    }
}

// ---------------------------------------------------------------------------
// K0a: x [b][c][n] -> transposed split xt hi/lo [b][n][c]
// ---------------------------------------------------------------------------
__global__ __launch_bounds__(256) void k_split_x(const float* __restrict__ x)
{
    __shared__ float t[32][33];
    int b = blockIdx.z;
    int n0 = blockIdx.x * 32, c0 = blockIdx.y * 32;
    int tx = threadIdx.x & 31, ty = threadIdx.x >> 5;

    const float* xb = x + (size_t)b * CH * HW;
    #pragma unroll
    for (int k = 0; k < 4; k++)
        t[ty + 8 * k][tx] = xb[(size_t)(c0 + ty + 8 * k) * HW + n0 + tx];
    __syncthreads();
    bf16* Xh = g_xth + (size_t)b * HW * CH;
    bf16* Xl = g_xtl + (size_t)b * HW * CH;
    #pragma unroll
    for (int k = 0; k < 4; k++) {
        float v = t[tx][ty + 8 * k];
        bf16 h, l; split2(v, h, l);
        size_t off = (size_t)(n0 + ty + 8 * k) * CH + c0 + tx;
        Xh[off] = h; Xl[off] = l;
    }
}

// K0b: split Wq,Wk,Wv into g_wh/g_wl
__global__ __launch_bounds__(256) void k_split_w(
    const float* __restrict__ Wq, const float* __restrict__ Wk, const float* __restrict__ Wv)
{
    int idx = blockIdx.x * 256 + threadIdx.x;
    int p = blockIdx.y;
    const float* W = (p == 0) ? Wq : ((p == 1) ? Wk : Wv);
    float v = W[idx];
    bf16 h, l; split2(v, h, l);
    g_wh[p * AD * CH + idx] = h;
    g_wl[p * AD * CH + idx] = l;
}

// ---------------------------------------------------------------------------
// K1: projections via split MMA (256 thr, 64x32 warp tiles, K32 2-deep).
// ---------------------------------------------------------------------------
__global__ __launch_bounds__(256) void k_proj_mma(
    const float* __restrict__ bq, const float* __restrict__ bk, const float* __restrict__ bv)
{
    MMA_PROLOG();
    int z = blockIdx.z;
    int b = z / 3, p = z % 3;
    int n0 = blockIdx.x * 128;
    int a0 = blockIdx.y * 128;

    const bf16* Ah = g_xth + ((size_t)b * HW + n0) * CH;
    const bf16* Al = g_xtl + ((size_t)b * HW + n0) * CH;
    const bf16* Bh = g_wh + (size_t)p * AD * CH + (size_t)a0 * CH;
    const bf16* Bl = g_wl + (size_t)p * AD * CH + (size_t)a0 * CH;
    const float* bias = (p == 0) ? bq : ((p == 1) ? bk : bv);

    MMA_MAINLOOP_SPLIT(Ah, Al, Bh, Bl, CH, CH, CH / 32);

    __syncthreads();   // mainloop smem dead; reuse as bounce buffer

    if (p < 2) {
        bf16* th = reinterpret_cast<bf16*>(smc);      // [128][136]
        bf16* tl = th + 128 * 136;
        #pragma unroll
        for (int j = 0; j < 4; j++) {
            int c2 = wn * 32 + j * 8 + tg * 2;
            float bb0 = bias[a0 + c2], bb1 = bias[a0 + c2 + 1];
            #pragma unroll
            for (int i = 0; i < 4; i++) {
                int nr = wm * 64 + i * 16 + g;
                #pragma unroll
                for (int half = 0; half < 2; half++) {
                    int nn = nr + half * 8;
                    float v0 = acc[i][j][half * 2 + 0] + bb0;
                    float v1 = acc[i][j][half * 2 + 1] + bb1;
                    bf16 h0, l0, h1, l1;
                    split2(v0, h0, l0); split2(v1, h1, l1);
                    __nv_bfloat162 hh; hh.x = h0; hh.y = h1;
                    __nv_bfloat162 ll; ll.x = l0; ll.y = l1;
                    *reinterpret_cast<__nv_bfloat162*>(&th[nn * 136 + c2]) = hh;
                    *reinterpret_cast<__nv_bfloat162*>(&tl[nn * 136 + c2]) = ll;
                }
            }
        }
        __syncthreads();
        bf16* Yh = ((p == 0) ? g_qh : g_kh) + (size_t)b * HW * AD;
        bf16* Yl = ((p == 0) ? g_ql : g_kl) + (size_t)b * HW * AD;
        int r = tid >> 1, part = tid & 1;
        size_t off = (size_t)(n0 + r) * AD + a0 + part * 64;
        const float4* sh4 = reinterpret_cast<const float4*>(th + r * 136 + part * 64);
        const float4* sl4 = reinterpret_cast<const float4*>(tl + r * 136 + part * 64);
        float4* dh4 = reinterpret_cast<float4*>(Yh + off);
        float4* dl4 = reinterpret_cast<float4*>(Yl + off);
        #pragma unroll
        for (int u = 0; u < 8; u++) { dh4[u] = sh4[u]; dl4[u] = sl4[u]; }
    } else {
        __half* th = reinterpret_cast<__half*>(smc);  // [128][136] transposed
        #pragma unroll
        for (int j = 0; j < 4; j++) {
            int c2 = wn * 32 + j * 8 + tg * 2;
            float bb0 = bias[a0 + c2], bb1 = bias[a0 + c2 + 1];
            #pragma unroll
            for (int i = 0; i < 4; i++) {
                int nr = wm * 64 + i * 16 + g;
                #pragma unroll
                for (int half = 0; half < 2; half++) {
                    int nn = nr + half * 8;
                    th[(c2 + 0) * 136 + nn] = __float2half_rn(acc[i][j][half * 2 + 0] + bb0);
                    th[(c2 + 1) * 136 + nn] = __float2half_rn(acc[i][j][half * 2 + 1] + bb1);
                }
            }
        }
        __syncthreads();
        __half* Tv = g_vt16 + (size_t)b * CH * HW;
        int r = tid >> 1, part = tid & 1;
        size_t off = (size_t)(a0 + r) * HW + n0 + part * 64;
        const float4* sh4 = reinterpret_cast<const float4*>(th + r * 136 + part * 64);
        float4* dh4 = reinterpret_cast<float4*>(Tv + off);
        #pragma unroll
        for (int u = 0; u < 8; u++) dh4[u] = sh4[u];
    }
}

// ---------------------------------------------------------------------------
// K2: S = Q K^T (bf16 split, 3 products), K32 2-deep mainloop.
// Epilogue: per-tile column max -> p_tile = exp(acc - M_tile) fp16, bounced
// through smem for coalesced row stores; per-tile stats to g_cmax/g_csum.
// ---------------------------------------------------------------------------
__global__ __launch_bounds__(256, 2) void k_scores_mma()
{
    MMA_PROLOG();
    int b = blockIdx.z;
    int m0 = blockIdx.x * 128;   // key block (cols)
    int n0 = blockIdx.y * 128;   // query block (rows)

    const bf16* Ah = g_qh + ((size_t)b * HW + n0) * AD;
    const bf16* Al = g_ql + ((size_t)b * HW + n0) * AD;
    const bf16* Bh = g_kh + ((size_t)b * HW + m0) * AD;
    const bf16* Bl = g_kl + ((size_t)b * HW + m0) * AD;

    MMA_MAINLOOP_SPLIT(Ah, Al, Bh, Bl, AD, AD, AD / 32);

    __syncthreads();   // mainloop smem dead; reuse for stats + bounce
    float* wmax = reinterpret_cast<float*>(smc);             // [2][128]
    float* wsum = wmax + 256;                                // [2][128]
    __half* pt  = reinterpret_cast<__half*>(smc + 2048);     // [128][136]

    // Phase 1: per-column tile max
    float cm[8];
    #pragma unroll
    for (int j = 0; j < 4; j++)
        #pragma unroll
        for (int p = 0; p < 2; p++) {
            float mv = -3.4e38f;
            #pragma unroll
            for (int i = 0; i < 4; i++) {
                mv = fmaxf(mv, acc[i][j][p]);
                mv = fmaxf(mv, acc[i][j][2 + p]);
            }
            cm[j * 2 + p] = mv;
        }
    #pragma unroll
    for (int idx = 0; idx < 8; idx++) {
        cm[idx] = fmaxf(cm[idx], __shfl_xor_sync(0xffffffffu, cm[idx], 4));
        cm[idx] = fmaxf(cm[idx], __shfl_xor_sync(0xffffffffu, cm[idx], 8));
        cm[idx] = fmaxf(cm[idx], __shfl_xor_sync(0xffffffffu, cm[idx], 16));
    }
    if (lane < 4) {
        #pragma unroll
        for (int j = 0; j < 4; j++)
            #pragma unroll
            for (int p = 0; p < 2; p++)
                wmax[wm * 128 + wn * 32 + j * 8 + tg * 2 + p] = cm[j * 2 + p];
    }
    __syncthreads();

    // Phase 2: exp -> smem bounce (half2 stores), accumulate sums
    float cs[8];
    #pragma unroll
    for (int j = 0; j < 4; j++) {
        int c2 = wn * 32 + j * 8 + tg * 2;
        float M0 = fmaxf(wmax[c2], wmax[128 + c2]);
        float M1 = fmaxf(wmax[c2 + 1], wmax[128 + c2 + 1]);
        float s0 = 0.f, s1 = 0.f;
        #pragma unroll
        for (int i = 0; i < 4; i++) {
            int nr = wm * 64 + i * 16 + g;
            #pragma unroll
            for (int half = 0; half < 2; half++) {
                int nn = nr + half * 8;
                float e0 = fast_exp_neg(acc[i][j][half * 2 + 0] - M0);
                float e1 = fast_exp_neg(acc[i][j][half * 2 + 1] - M1);
                s0 += e0; s1 += e1;
                __half2 hv; hv.x = __float2half_rn(e0); hv.y = __float2half_rn(e1);
                *reinterpret_cast<__half2*>(&pt[nn * 136 + c2]) = hv;
            }
        }
        cs[j * 2 + 0] = s0;
        cs[j * 2 + 1] = s1;
    }
    #pragma unroll
    for (int idx = 0; idx < 8; idx++) {
        cs[idx] += __shfl_xor_sync(0xffffffffu, cs[idx], 4);
        cs[idx] += __shfl_xor_sync(0xffffffffu, cs[idx], 8);
        cs[idx] += __shfl_xor_sync(0xffffffffu, cs[idx], 16);
    }
    if (lane < 4) {
        #pragma unroll
        for (int j = 0; j < 4; j++)
            #pragma unroll
            for (int p = 0; p < 2; p++)
                wsum[wm * 128 + wn * 32 + j * 8 + tg * 2 + p] = cs[j * 2 + p];
    }
    __syncthreads();

    // stats out
    if (tid < 128) {
        int c = tid;
        float M = fmaxf(wmax[c], wmax[128 + c]);
        float S_ = wsum[c] + wsum[128 + c];
        size_t si = ((size_t)b * 32 + (n0 >> 7)) * HW + m0 + c;
        g_cmax[si] = M;
        g_csum[si] = S_;
    }

    // coalesced P copy: 2 threads per row, 64 halves (128 B) each
    __half* Pb = g_p16 + (size_t)b * HW * HW;
    int r = tid >> 1, part = tid & 1;
    const float4* s4 = reinterpret_cast<const float4*>(pt + r * 136 + part * 64);
    float4* d4 = reinterpret_cast<float4*>(Pb + (size_t)(n0 + r) * HW + m0 + part * 64);
    #pragma unroll
    for (int u = 0; u < 8; u++) d4[u] = s4[u];
}

// ---------------------------------------------------------------------------
// K3: column softmax finalize. Merge tile stats -> per-(tile,col) scale
// factor, then in-place rescale of g_p16 (no S buffer, no exp pass).
// ---------------------------------------------------------------------------
__global__ __launch_bounds__(256) void k_softmax()
{
    int b = blockIdx.y;
    int col = threadIdx.x & 63;
    int m = blockIdx.x * 64 + col;
    int rq = threadIdx.x >> 6;
    __half* Pb = g_p16 + (size_t)b * HW * HW;

    float m2s[8];
    float mx = -3.4e38f, den = 0.f;
    #pragma unroll
    for (int t = 0; t < 8; t++) {
        int tn = rq * 8 + t;
        size_t si = ((size_t)b * 32 + tn) * HW + m;
        float m2 = g_cmax[si];
        float d2 = g_csum[si];
        m2s[t] = m2;
        float nm = fmaxf(mx, m2);
        den = den * fast_exp_neg(mx - nm) + d2 * fast_exp_neg(m2 - nm);
        mx = nm;
    }

    __shared__ float smx[256], sden[256];
    __shared__ float cmx[64], cinv[64];
    smx[threadIdx.x] = mx; sden[threadIdx.x] = den;
    __syncthreads();
    if (threadIdx.x < 64) {
        float M = smx[threadIdx.x], D = sden[threadIdx.x];
        #pragma unroll
        for (int k = 1; k < 4; k++) {
            float m2 = smx[threadIdx.x + 64 * k], d2 = sden[threadIdx.x + 64 * k];
            float nm = fmaxf(M, m2);
            D = D * fast_exp_neg(M - nm) + d2 * fast_exp_neg(m2 - nm);
            M = nm;
        }
        cmx[threadIdx.x] = M;
        cinv[threadIdx.x] = 1.0f / D;
    }
    __syncthreads();
    float M = cmx[col], inv = cinv[col];

    // in-place rescale: P = p_tile * exp(M_tile - M) * inv
    #pragma unroll
    for (int t = 0; t < 8; t++) {
        float fac = fast_exp_neg(m2s[t] - M) * inv;
        int base = (rq * 8 + t) * 128;
        for (int n = base; n < base + 128; n += 8) {
            float v[8];
            #pragma unroll
            for (int u = 0; u < 8; u++)
                v[u] = __half2float(Pb[(size_t)(n + u) * HW + m]);
            #pragma unroll
            for (int u = 0; u < 8; u++)
                Pb[(size_t)(n + u) * HW + m] = __float2half_rn(v[u] * fac);
        }
    }
}

// ---------------------------------------------------------------------------
// K4: O = P V (fp16 single product) + residual. K=4096, 64 stages of 64,
// 3-deep cp.async pipeline (wait_group 1).
// ---------------------------------------------------------------------------
__global__ __launch_bounds__(256) void k_out_mma(
    const float* __restrict__ x, float* __restrict__ out)
{
    MMA_PROLOG();
    int b = blockIdx.z;
    int c0 = blockIdx.x * 128;
    int n0 = blockIdx.y * 128;

    const __half* A = g_p16 + (size_t)b * HW * HW + (size_t)n0 * HW;
    const __half* B = g_vt16 + ((size_t)b * CH + c0) * HW;

    stage_load_o64(sb, 0, A, B, HW, HW, 0, tid);
    stage_load_o64(sb, 1, A, B, HW, HW, 64, tid);
    const int KS = HW / 64;
    for (int s = 0; s < KS; s++) {
        cp_wait1();
        __syncthreads();
        if (s + 2 < KS)
            stage_load_o64(sb, (s + 2) % 3, A, B, HW, HW, (s + 2) * 64, tid);
        else
            cp_commit();
        stage_mma_o64(sb + (s % 3) * OT_STAGE_B, acc, wm, wn, lane);
    }

    const float* xb = x + (size_t)b * CH * HW;
    float* ob = out + (size_t)b * CH * HW;
    #pragma unroll
    for (int i = 0; i < 4; i++) {
        int n = n0 + wm * 64 + i * 16 + g;
        #pragma unroll
        for (int j = 0; j < 4; j++) {
            int c = c0 + wn * 32 + j * 8 + tg * 2;
            {
                size_t off = (size_t)n * CH + c;
                float2 xv = *reinterpret_cast<const float2*>(&xb[off]);
                *reinterpret_cast<float2*>(&ob[off]) =
                    make_float2(fmaf(0.1f, acc[i][j][0], xv.x),
                                fmaf(0.1f, acc[i][j][1], xv.y));
            }
            {
                size_t off = (size_t)(n + 8) * CH + c;
                float2 xv = *reinterpret_cast<const float2*>(&xb[off]);
                *reinterpret_cast<float2*>(&ob[off]) =
                    make_float2(fmaf(0.1f, acc[i][j][2], xv.x),
                                fmaf(0.1f, acc[i][j][3], xv.y));
            }
        }
    }
}

// ---------------------------------------------------------------------------
extern "C" void kernel_launch(void* const* d_in, const int* in_sizes, int n_in,
                              void* d_out, int out_size)
{
    const float* x  = (const float*)d_in[0];
    const float* Wq = (const float*)d_in[1];
    const float* bq = (const float*)d_in[2];
    const float* Wk = (const float*)d_in[3];
    const float* bk = (const float*)d_in[4];
    const float* Wv = (const float*)d_in[5];
    const float* bv = (const float*)d_in[6];
    float* out = (float*)d_out;

    static int configured = 0;
    if (!configured) {
        cudaFuncSetAttribute(k_proj_mma,   cudaFuncAttributeMaxDynamicSharedMemorySize, SMEM_GEMM);
        cudaFuncSetAttribute(k_scores_mma, cudaFuncAttributeMaxDynamicSharedMemorySize, SMEM_GEMM);
        cudaFuncSetAttribute(k_out_mma,    cudaFuncAttributeMaxDynamicSharedMemorySize, OT_SMEM);
        configured = 1;
    }

    k_split_x   <<<dim3(HW / 32, CH / 32, BATCH), 256>>>(x);
    k_split_w   <<<dim3(AD * CH / 256, 3), 256>>>(Wq, Wk, Wv);
    k_proj_mma  <<<dim3(HW / 128, AD / 128, BATCH * 3), 256, SMEM_GEMM>>>(bq, bk, bv);
    k_scores_mma<<<dim3(HW / 128, HW / 128, BATCH), 256, SMEM_GEMM>>>();
    k_softmax   <<<dim3(HW / 64, BATCH), 256>>>();
    k_out_mma   <<<dim3(CH / 128, HW / 128, BATCH), 256, OT_SMEM>>>(x, out);
}

// round 16
// speedup vs baseline: 1.2239x; 1.1353x over previous
#include <cuda_runtime.h>
#include <cuda_bf16.h>
#include <cuda_fp16.h>
#include <cstdint>

#define BATCH 4
#define CH    512
#define HW    4096
#define AD    512

typedef __nv_bfloat16 bf16;

// ---------------- scratch (__device__ globals; no allocation) ---------------
__device__ bf16 g_xth[BATCH * HW * CH];          // x^T [b][n][c] hi
__device__ bf16 g_xtl[BATCH * HW * CH];          // lo
__device__ bf16 g_wh[3 * AD * CH];               // Wq,Wk,Wv hi
__device__ bf16 g_wl[3 * AD * CH];               // lo
__device__ __half g_q16[BATCH * HW * AD];        // q fp16 (single)
__device__ __half g_kh16[BATCH * HW * AD];       // k fp16 hi
__device__ __half g_kl16[BATCH * HW * AD];       // k fp16 lo
__device__ __half g_vt16[BATCH * CH * HW];       // v^T [b][c][n], fp16
__device__ __half g_p16[(size_t)BATCH * HW * HW]; // tile-normalized probs fp16
__device__ float g_cmax[BATCH * 32 * HW];        // per-row-tile column max
__device__ float g_csum[BATCH * 32 * HW];        // per-row-tile column sumexp

// ---------------- helpers ----------------------------------------------------
__device__ __forceinline__ uint32_t smem_u32(const void* p) {
    uint32_t a;
    asm("{ .reg .u64 t; cvta.to.shared.u64 t, %1; cvt.u32.u64 %0, t; }" : "=r"(a) : "l"(p));
    return a;
}
__device__ __forceinline__ void cp16(uint32_t d, const void* s) {
    asm volatile("cp.async.ca.shared.global [%0], [%1], 16;" :: "r"(d), "l"(s));
}
__device__ __forceinline__ void cp_commit() { asm volatile("cp.async.commit_group;" ::: "memory"); }
__device__ __forceinline__ void cp_wait0()  { asm volatile("cp.async.wait_group 0;" ::: "memory"); }
__device__ __forceinline__ void cp_wait1()  { asm volatile("cp.async.wait_group 1;" ::: "memory"); }

__device__ __forceinline__ void ldsm4(uint32_t* r, uint32_t addr) {
    asm volatile("ldmatrix.sync.aligned.m8n8.x4.shared.b16 {%0,%1,%2,%3}, [%4];"
        : "=r"(r[0]), "=r"(r[1]), "=r"(r[2]), "=r"(r[3]) : "r"(addr));
}

__device__ __forceinline__ void mma16816(float* c,
    uint32_t a0, uint32_t a1, uint32_t a2, uint32_t a3, uint32_t b0, uint32_t b1)
{
    asm volatile(
        "mma.sync.aligned.m16n8k16.row.col.f32.bf16.bf16.f32 "
        "{%0,%1,%2,%3},{%4,%5,%6,%7},{%8,%9},{%0,%1,%2,%3};"
        : "+f"(c[0]), "+f"(c[1]), "+f"(c[2]), "+f"(c[3])
        : "r"(a0), "r"(a1), "r"(a2), "r"(a3), "r"(b0), "r"(b1));
}
__device__ __forceinline__ void mma16816h(float* c,
    uint32_t a0, uint32_t a1, uint32_t a2, uint32_t a3, uint32_t b0, uint32_t b1)
{
    asm volatile(
        "mma.sync.aligned.m16n8k16.row.col.f32.f16.f16.f32 "
        "{%0,%1,%2,%3},{%4,%5,%6,%7},{%8,%9},{%0,%1,%2,%3};"
        : "+f"(c[0]), "+f"(c[1]), "+f"(c[2]), "+f"(c[3])
        : "r"(a0), "r"(a1), "r"(a2), "r"(a3), "r"(b0), "r"(b1));
}

// FMA-only exp (x <= 0)
__device__ __forceinline__ float fast_exp_neg(float x) {
    float t = x * 1.4426950408889634f;
    t = fmaxf(t, -126.0f);
    float r = rintf(t);
    float f = t - r;
    float p = 1.3333558e-3f;
    p = fmaf(p, f, 9.6181291e-3f);
    p = fmaf(p, f, 5.5504110e-2f);
    p = fmaf(p, f, 2.4022651e-1f);
    p = fmaf(p, f, 6.9314718e-1f);
    p = fmaf(p, f, 1.0f);
    return __int_as_float(__float_as_int(p) + ((int)r << 23));
}

__device__ __forceinline__ void split2(float v, bf16& h, bf16& l) {
    h = __float2bfloat16(v);
    l = __float2bfloat16(v - __bfloat162float(h));
}
__device__ __forceinline__ void split2h(float v, __half& h, __half& l) {
    h = __float2half_rn(v);
    l = __float2half_rn(v - __half2float(h));
}

// ---------------- proj smem layout: K=32 stages, double-buffered, 4 tiles ----
#define TT      40
#define TILE_B  10240
#define STAGE_B 40960
#define SMEM_GEMM (2 * STAGE_B)   // 81920

__device__ __forceinline__ void stage_load32(uint32_t sb, int st,
    const bf16* __restrict__ Ah, const bf16* __restrict__ Al,
    const bf16* __restrict__ Bh, const bf16* __restrict__ Bl,
    int ldA, int ldB, int k0, int tid)
{
    int row = tid >> 1;
    int h0  = (tid & 1) * 16;
    uint32_t d = sb + st * STAGE_B + row * 80 + h0 * 2;
    const size_t oA = (size_t)row * ldA + k0 + h0;
    const size_t oB = (size_t)row * ldB + k0 + h0;
    cp16(d + 0 * TILE_B,      Ah + oA); cp16(d + 0 * TILE_B + 16, Ah + oA + 8);
    cp16(d + 1 * TILE_B,      Al + oA); cp16(d + 1 * TILE_B + 16, Al + oA + 8);
    cp16(d + 2 * TILE_B,      Bh + oB); cp16(d + 2 * TILE_B + 16, Bh + oB + 8);
    cp16(d + 3 * TILE_B,      Bl + oB); cp16(d + 3 * TILE_B + 16, Bl + oB + 8);
    cp_commit();
}

__device__ __forceinline__ void stage_mma32(uint32_t sst, float acc[4][4][4],
                                            int wm, int wn, int lane)
{
    int lane8 = lane & 7, seg = lane >> 3;
    int arow = (seg & 1) << 3, acol = (seg >> 1) << 3;
    int brow = (seg >> 1) << 3, bcol = (seg & 1) << 3;

    #pragma unroll
    for (int kh = 0; kh < 2; kh++) {
        int ko = kh * 16;
        uint32_t ah[4][4], bh[4][2];
        #pragma unroll
        for (int i = 0; i < 4; i++) {
            int r = wm * 64 + i * 16 + lane8 + arow;
            ldsm4(ah[i], sst + 0 * TILE_B + (uint32_t)(r * TT + ko + acol) * 2);
        }
        #pragma unroll
        for (int jp = 0; jp < 2; jp++) {
            int r = wn * 32 + jp * 16 + lane8 + brow;
            uint32_t t[4];
            ldsm4(t, sst + 2 * TILE_B + (uint32_t)(r * TT + ko + bcol) * 2);
            bh[jp * 2][0] = t[0];     bh[jp * 2][1] = t[1];
            bh[jp * 2 + 1][0] = t[2]; bh[jp * 2 + 1][1] = t[3];
        }
        #pragma unroll
        for (int i = 0; i < 4; i++)
            #pragma unroll
            for (int j = 0; j < 4; j++)
                mma16816(acc[i][j], ah[i][0], ah[i][1], ah[i][2], ah[i][3], bh[j][0], bh[j][1]);

        uint32_t bl[4][2];
        #pragma unroll
        for (int jp = 0; jp < 2; jp++) {
            int r = wn * 32 + jp * 16 + lane8 + brow;
            uint32_t t[4];
            ldsm4(t, sst + 3 * TILE_B + (uint32_t)(r * TT + ko + bcol) * 2);
            bl[jp * 2][0] = t[0];     bl[jp * 2][1] = t[1];
            bl[jp * 2 + 1][0] = t[2]; bl[jp * 2 + 1][1] = t[3];
        }
        #pragma unroll
        for (int i = 0; i < 4; i++)
            #pragma unroll
            for (int j = 0; j < 4; j++)
                mma16816(acc[i][j], ah[i][0], ah[i][1], ah[i][2], ah[i][3], bl[j][0], bl[j][1]);

        uint32_t al[4][4];
        #pragma unroll
        for (int i = 0; i < 4; i++) {
            int r = wm * 64 + i * 16 + lane8 + arow;
            ldsm4(al[i], sst + 1 * TILE_B + (uint32_t)(r * TT + ko + acol) * 2);
        }
        #pragma unroll
        for (int i = 0; i < 4; i++)
            #pragma unroll
            for (int j = 0; j < 4; j++)
                mma16816(acc[i][j], al[i][0], al[i][1], al[i][2], al[i][3], bh[j][0], bh[j][1]);
    }
}

#define MMA_PROLOG()                                                             \
    extern __shared__ char smc[];                                                \
    uint32_t sb = smem_u32(smc);                                                 \
    int tid = threadIdx.x, lane = tid & 31, wid = tid >> 5;                      \
    int wm = wid & 1, wn = wid >> 1, g = lane >> 2, tg = lane & 3;               \
    float acc[4][4][4];                                                          \
    _Pragma("unroll")                                                            \
    for (int i = 0; i < 4; i++)                                                  \
        _Pragma("unroll")                                                        \
        for (int j = 0; j < 4; j++)                                              \
            _Pragma("unroll")                                                    \
            for (int r = 0; r < 4; r++) acc[i][j][r] = 0.f;

#define MMA_MAINLOOP_SPLIT(Ah, Al, Bh, Bl, ldA, ldB, KS)                         \
    stage_load32(sb, 0, Ah, Al, Bh, Bl, ldA, ldB, 0, tid);                       \
    for (int s = 0; s < (KS); s++) {                                             \
        cp_wait0();                                                              \
        __syncthreads();                                                         \
        if (s + 1 < (KS))                                                        \
            stage_load32(sb, (s + 1) & 1, Ah, Al, Bh, Bl, ldA, ldB,              \
                         (s + 1) * 32, tid);                                     \
        stage_mma32(sb + (s & 1) * STAGE_B, acc, wm, wn, lane);                  \
    }

// ---------------- scores smem layout: K=32 stages, double-buffered, 3 tiles --
#define SC_TILE_B  10240
#define SC_STAGE_B 30720
#define SC_SMEM    (2 * SC_STAGE_B)   // 61440

__device__ __forceinline__ void stage_load32s(uint32_t sb, int st,
    const __half* __restrict__ A, const __half* __restrict__ Bh,
    const __half* __restrict__ Bl, int ld, int k0, int tid)
{
    int row = tid >> 1;
    int h0  = (tid & 1) * 16;
    uint32_t d = sb + st * SC_STAGE_B + row * 80 + h0 * 2;
    const size_t o = (size_t)row * ld + k0 + h0;
    cp16(d + 0 * SC_TILE_B,      A  + o); cp16(d + 0 * SC_TILE_B + 16, A  + o + 8);
    cp16(d + 1 * SC_TILE_B,      Bh + o); cp16(d + 1 * SC_TILE_B + 16, Bh + o + 8);
    cp16(d + 2 * SC_TILE_B,      Bl + o); cp16(d + 2 * SC_TILE_B + 16, Bl + o + 8);
    cp_commit();
}

__device__ __forceinline__ void stage_mma32s(uint32_t sst, float acc[4][4][4],
                                             int wm, int wn, int lane)
{
    int lane8 = lane & 7, seg = lane >> 3;
    int arow = (seg & 1) << 3, acol = (seg >> 1) << 3;
    int brow = (seg >> 1) << 3, bcol = (seg & 1) << 3;

    #pragma unroll
    for (int kh = 0; kh < 2; kh++) {
        int ko = kh * 16;
        uint32_t ah[4][4], bh[4][2];
        #pragma unroll
        for (int i = 0; i < 4; i++) {
            int r = wm * 64 + i * 16 + lane8 + arow;
            ldsm4(ah[i], sst + 0 * SC_TILE_B + (uint32_t)(r * TT + ko + acol) * 2);
        }
        #pragma unroll
        for (int jp = 0; jp < 2; jp++) {
            int r = wn * 32 + jp * 16 + lane8 + brow;
            uint32_t t[4];
            ldsm4(t, sst + 1 * SC_TILE_B + (uint32_t)(r * TT + ko + bcol) * 2);
            bh[jp * 2][0] = t[0];     bh[jp * 2][1] = t[1];
            bh[jp * 2 + 1][0] = t[2]; bh[jp * 2 + 1][1] = t[3];
        }
        #pragma unroll
        for (int i = 0; i < 4; i++)
            #pragma unroll
            for (int j = 0; j < 4; j++)
                mma16816h(acc[i][j], ah[i][0], ah[i][1], ah[i][2], ah[i][3], bh[j][0], bh[j][1]);

        uint32_t bl[4][2];
        #pragma unroll
        for (int jp = 0; jp < 2; jp++) {
            int r = wn * 32 + jp * 16 + lane8 + brow;
            uint32_t t[4];
            ldsm4(t, sst + 2 * SC_TILE_B + (uint32_t)(r * TT + ko + bcol) * 2);
            bl[jp * 2][0] = t[0];     bl[jp * 2][1] = t[1];
            bl[jp * 2 + 1][0] = t[2]; bl[jp * 2 + 1][1] = t[3];
        }
        #pragma unroll
        for (int i = 0; i < 4; i++)
            #pragma unroll
            for (int j = 0; j < 4; j++)
                mma16816h(acc[i][j], ah[i][0], ah[i][1], ah[i][2], ah[i][3], bl[j][0], bl[j][1]);
    }
}

// ---------------- k_out smem layout: fp16, 2 tiles, K=64, 3-deep pipeline ----
#define TTO        72
#define OT_TILE_B  18432
#define OT_STAGE_B 36864
#define OT_SMEM    (3 * OT_STAGE_B)   // 110592 -> 2 CTA/SM

__device__ __forceinline__ void stage_load_o64(uint32_t sb, int st,
    const __half* __restrict__ A, const __half* __restrict__ B,
    int ldA, int ldB, int k0, int tid)
{
    int row = tid >> 1;
    int seg = tid & 1;
    uint32_t d = sb + st * OT_STAGE_B + row * 144 + seg * 64;
    const size_t oA = (size_t)row * ldA + k0 + seg * 32;
    const size_t oB = (size_t)row * ldB + k0 + seg * 32;
    #pragma unroll
    for (int u = 0; u < 4; u++) {
        cp16(d + u * 16,              A + oA + u * 8);
        cp16(d + OT_TILE_B + u * 16,  B + oB + u * 8);
    }
    cp_commit();
}

__device__ __forceinline__ void stage_mma_o64(uint32_t sst, float acc[4][4][4],
                                              int wm, int wn, int lane)
{
    int lane8 = lane & 7, seg = lane >> 3;
    int arow = (seg & 1) << 3, acol = (seg >> 1) << 3;
    int brow = (seg >> 1) << 3, bcol = (seg & 1) << 3;

    #pragma unroll
    for (int kh = 0; kh < 4; kh++) {
        int ko = kh * 16;
        uint32_t a[4][4], b[4][2];
        #pragma unroll
        for (int i = 0; i < 4; i++) {
            int r = wm * 64 + i * 16 + lane8 + arow;
            ldsm4(a[i], sst + (uint32_t)(r * TTO + ko + acol) * 2);
        }
        #pragma unroll
        for (int jp = 0; jp < 2; jp++) {
            int r = wn * 32 + jp * 16 + lane8 + brow;
            uint32_t t[4];
            ldsm4(t, sst + OT_TILE_B + (uint32_t)(r * TTO + ko + bcol) * 2);
            b[jp * 2][0] = t[0];     b[jp * 2][1] = t[1];
            b[jp * 2 + 1][0] = t[2]; b[jp * 2 + 1][1] = t[3];
        }
        #pragma unroll
        for (int i = 0; i < 4; i++)
            #pragma unroll
            for (int j = 0; j < 4; j++)
                mma16816h(acc[i][j], a[i][0], a[i][1], a[i][2], a[i][3], b[j][0], b[j][1]);
    }
}

// ---------------------------------------------------------------------------
// K0a: x [b][c][n] -> transposed split xt hi/lo [b][n][c]
// ---------------------------------------------------------------------------
__global__ __launch_bounds__(256) void k_split_x(const float* __restrict__ x)
{
    __shared__ float t[32][33];
    int b = blockIdx.z;
    int n0 = blockIdx.x * 32, c0 = blockIdx.y * 32;
    int tx = threadIdx.x & 31, ty = threadIdx.x >> 5;

    const float* xb = x + (size_t)b * CH * HW;
    #pragma unroll
    for (int k = 0; k < 4; k++)
        t[ty + 8 * k][tx] = xb[(size_t)(c0 + ty + 8 * k) * HW + n0 + tx];
    __syncthreads();
    bf16* Xh = g_xth + (size_t)b * HW * CH;
    bf16* Xl = g_xtl + (size_t)b * HW * CH;
    #pragma unroll
    for (int k = 0; k < 4; k++) {
        float v = t[tx][ty + 8 * k];
        bf16 h, l; split2(v, h, l);
        size_t off = (size_t)(n0 + ty + 8 * k) * CH + c0 + tx;
        Xh[off] = h; Xl[off] = l;
    }
}

// K0b: split Wq,Wk,Wv into g_wh/g_wl
__global__ __launch_bounds__(256) void k_split_w(
    const float* __restrict__ Wq, const float* __restrict__ Wk, const float* __restrict__ Wv)
{
    int idx = blockIdx.x * 256 + threadIdx.x;
    int p = blockIdx.y;
    const float* W = (p == 0) ? Wq : ((p == 1) ? Wk : Wv);
    float v = W[idx];
    bf16 h, l; split2(v, h, l);
    g_wh[p * AD * CH + idx] = h;
    g_wl[p * AD * CH + idx] = l;
}

// ---------------------------------------------------------------------------
// K1: projections via split MMA (256 thr, 64x32 warp tiles, K32 2-deep).
// Epilogues: q -> fp16 single; k -> fp16 hi/lo; v -> fp16 transposed.
// ---------------------------------------------------------------------------
__global__ __launch_bounds__(256) void k_proj_mma(
    const float* __restrict__ bq, const float* __restrict__ bk, const float* __restrict__ bv)
{
    MMA_PROLOG();
    int z = blockIdx.z;
    int b = z / 3, p = z % 3;
    int n0 = blockIdx.x * 128;
    int a0 = blockIdx.y * 128;

    const bf16* Ah = g_xth + ((size_t)b * HW + n0) * CH;
    const bf16* Al = g_xtl + ((size_t)b * HW + n0) * CH;
    const bf16* Bh = g_wh + (size_t)p * AD * CH + (size_t)a0 * CH;
    const bf16* Bl = g_wl + (size_t)p * AD * CH + (size_t)a0 * CH;
    const float* bias = (p == 0) ? bq : ((p == 1) ? bk : bv);

    MMA_MAINLOOP_SPLIT(Ah, Al, Bh, Bl, CH, CH, CH / 32);

    __syncthreads();   // mainloop smem dead; reuse as bounce buffer

    if (p == 0) {
        // q: single fp16 tile [n][a]
        __half* th = reinterpret_cast<__half*>(smc);   // [128][136]
        #pragma unroll
        for (int j = 0; j < 4; j++) {
            int c2 = wn * 32 + j * 8 + tg * 2;
            float bb0 = bias[a0 + c2], bb1 = bias[a0 + c2 + 1];
            #pragma unroll
            for (int i = 0; i < 4; i++) {
                int nr = wm * 64 + i * 16 + g;
                #pragma unroll
                for (int half = 0; half < 2; half++) {
                    int nn = nr + half * 8;
                    __half2 hv;
                    hv.x = __float2half_rn(acc[i][j][half * 2 + 0] + bb0);
                    hv.y = __float2half_rn(acc[i][j][half * 2 + 1] + bb1);
                    *reinterpret_cast<__half2*>(&th[nn * 136 + c2]) = hv;
                }
            }
        }
        __syncthreads();
        __half* Y = g_q16 + (size_t)b * HW * AD;
        int r = tid >> 1, part = tid & 1;
        size_t off = (size_t)(n0 + r) * AD + a0 + part * 64;
        const float4* s4 = reinterpret_cast<const float4*>(th + r * 136 + part * 64);
        float4* d4 = reinterpret_cast<float4*>(Y + off);
        #pragma unroll
        for (int u = 0; u < 8; u++) d4[u] = s4[u];
    } else if (p == 1) {
        // k: fp16 hi/lo tiles [n][a]
        __half* th = reinterpret_cast<__half*>(smc);   // [128][136]
        __half* tl = th + 128 * 136;
        #pragma unroll
        for (int j = 0; j < 4; j++) {
            int c2 = wn * 32 + j * 8 + tg * 2;
            float bb0 = bias[a0 + c2], bb1 = bias[a0 + c2 + 1];
            #pragma unroll
            for (int i = 0; i < 4; i++) {
                int nr = wm * 64 + i * 16 + g;
                #pragma unroll
                for (int half = 0; half < 2; half++) {
                    int nn = nr + half * 8;
                    __half h0, l0, h1, l1;
                    split2h(acc[i][j][half * 2 + 0] + bb0, h0, l0);
                    split2h(acc[i][j][half * 2 + 1] + bb1, h1, l1);
                    __half2 hv; hv.x = h0; hv.y = h1;
                    __half2 lv; lv.x = l0; lv.y = l1;
                    *reinterpret_cast<__half2*>(&th[nn * 136 + c2]) = hv;
                    *reinterpret_cast<__half2*>(&tl[nn * 136 + c2]) = lv;
                }
            }
        }
        __syncthreads();
        __half* Yh = g_kh16 + (size_t)b * HW * AD;
        __half* Yl = g_kl16 + (size_t)b * HW * AD;
        int r = tid >> 1, part = tid & 1;
        size_t off = (size_t)(n0 + r) * AD + a0 + part * 64;
        const float4* sh4 = reinterpret_cast<const float4*>(th + r * 136 + part * 64);
        const float4* sl4 = reinterpret_cast<const float4*>(tl + r * 136 + part * 64);
        float4* dh4 = reinterpret_cast<float4*>(Yh + off);
        float4* dl4 = reinterpret_cast<float4*>(Yl + off);
        #pragma unroll
        for (int u = 0; u < 8; u++) { dh4[u] = sh4[u]; dl4[u] = sl4[u]; }
    } else {
        // v: fp16 transposed [c][n]
        __half* th = reinterpret_cast<__half*>(smc);  // [128][136] transposed
        #pragma unroll
        for (int j = 0; j < 4; j++) {
            int c2 = wn * 32 + j * 8 + tg * 2;
            float bb0 = bias[a0 + c2], bb1 = bias[a0 + c2 + 1];
            #pragma unroll
            for (int i = 0; i < 4; i++) {
                int nr = wm * 64 + i * 16 + g;
                #pragma unroll
                for (int half = 0; half < 2; half++) {
                    int nn = nr + half * 8;
                    th[(c2 + 0) * 136 + nn] = __float2half_rn(acc[i][j][half * 2 + 0] + bb0);
                    th[(c2 + 1) * 136 + nn] = __float2half_rn(acc[i][j][half * 2 + 1] + bb1);
                }
            }
        }
        __syncthreads();
        __half* Tv = g_vt16 + (size_t)b * CH * HW;
        int r = tid >> 1, part = tid & 1;
        size_t off = (size_t)(a0 + r) * HW + n0 + part * 64;
        const float4* sh4 = reinterpret_cast<const float4*>(th + r * 136 + part * 64);
        float4* dh4 = reinterpret_cast<float4*>(Tv + off);
        #pragma unroll
        for (int u = 0; u < 8; u++) dh4[u] = sh4[u];
    }
}

// ---------------------------------------------------------------------------
// K2: S = q (kh + kl)^T, fp16 2-product, K32 2-deep, 3 tiles/stage.
// Epilogue: per-tile column max -> p_tile fp16 via smem bounce + stats.
// ---------------------------------------------------------------------------
__global__ __launch_bounds__(256, 2) void k_scores_mma()
{
    MMA_PROLOG();
    int b = blockIdx.z;
    int m0 = blockIdx.x * 128;   // key block (cols)
    int n0 = blockIdx.y * 128;   // query block (rows)

    const __half* A  = g_q16  + ((size_t)b * HW + n0) * AD;
    const __half* Bh = g_kh16 + ((size_t)b * HW + m0) * AD;
    const __half* Bl = g_kl16 + ((size_t)b * HW + m0) * AD;

    stage_load32s(sb, 0, A, Bh, Bl, AD, 0, tid);
    const int KS = AD / 32;
    for (int s = 0; s < KS; s++) {
        cp_wait0();
        __syncthreads();
        if (s + 1 < KS)
            stage_load32s(sb, (s + 1) & 1, A, Bh, Bl, AD, (s + 1) * 32, tid);
        stage_mma32s(sb + (s & 1) * SC_STAGE_B, acc, wm, wn, lane);
    }

    __syncthreads();   // mainloop smem dead; reuse for stats + bounce
    float* wmax = reinterpret_cast<float*>(smc);             // [2][128]
    float* wsum = wmax + 256;                                // [2][128]
    __half* pt  = reinterpret_cast<__half*>(smc + 2048);     // [128][136]

    // Phase 1: per-column tile max
    float cm[8];
    #pragma unroll
    for (int j = 0; j < 4; j++)
        #pragma unroll
        for (int p = 0; p < 2; p++) {
            float mv = -3.4e38f;
            #pragma unroll
            for (int i = 0; i < 4; i++) {
                mv = fmaxf(mv, acc[i][j][p]);
                mv = fmaxf(mv, acc[i][j][2 + p]);
            }
            cm[j * 2 + p] = mv;
        }
    #pragma unroll
    for (int idx = 0; idx < 8; idx++) {
        cm[idx] = fmaxf(cm[idx], __shfl_xor_sync(0xffffffffu, cm[idx], 4));
        cm[idx] = fmaxf(cm[idx], __shfl_xor_sync(0xffffffffu, cm[idx], 8));
        cm[idx] = fmaxf(cm[idx], __shfl_xor_sync(0xffffffffu, cm[idx], 16));
    }
    if (lane < 4) {
        #pragma unroll
        for (int j = 0; j < 4; j++)
            #pragma unroll
            for (int p = 0; p < 2; p++)
                wmax[wm * 128 + wn * 32 + j * 8 + tg * 2 + p] = cm[j * 2 + p];
    }
    __syncthreads();

    // Phase 2: exp -> smem bounce (half2 stores), accumulate sums
    float cs[8];
    #pragma unroll
    for (int j = 0; j < 4; j++) {
        int c2 = wn * 32 + j * 8 + tg * 2;
        float M0 = fmaxf(wmax[c2], wmax[128 + c2]);
        float M1 = fmaxf(wmax[c2 + 1], wmax[128 + c2 + 1]);
        float s0 = 0.f, s1 = 0.f;
        #pragma unroll
        for (int i = 0; i < 4; i++) {
            int nr = wm * 64 + i * 16 + g;
            #pragma unroll
            for (int half = 0; half < 2; half++) {
                int nn = nr + half * 8;
                float e0 = fast_exp_neg(acc[i][j][half * 2 + 0] - M0);
                float e1 = fast_exp_neg(acc[i][j][half * 2 + 1] - M1);
                s0 += e0; s1 += e1;
                __half2 hv; hv.x = __float2half_rn(e0); hv.y = __float2half_rn(e1);
                *reinterpret_cast<__half2*>(&pt[nn * 136 + c2]) = hv;
            }
        }
        cs[j * 2 + 0] = s0;
        cs[j * 2 + 1] = s1;
    }
    #pragma unroll
    for (int idx = 0; idx < 8; idx++) {
        cs[idx] += __shfl_xor_sync(0xffffffffu, cs[idx], 4);
        cs[idx] += __shfl_xor_sync(0xffffffffu, cs[idx], 8);
        cs[idx] += __shfl_xor_sync(0xffffffffu, cs[idx], 16);
    }
    if (lane < 4) {
        #pragma unroll
        for (int j = 0; j < 4; j++)
            #pragma unroll
            for (int p = 0; p < 2; p++)
                wsum[wm * 128 + wn * 32 + j * 8 + tg * 2 + p] = cs[j * 2 + p];
    }
    __syncthreads();

    if (tid < 128) {
        int c = tid;
        float M = fmaxf(wmax[c], wmax[128 + c]);
        float S_ = wsum[c] + wsum[128 + c];
        size_t si = ((size_t)b * 32 + (n0 >> 7)) * HW + m0 + c;
        g_cmax[si] = M;
        g_csum[si] = S_;
    }

    // coalesced P copy: 2 threads per row, 64 halves (128 B) each
    __half* Pb = g_p16 + (size_t)b * HW * HW;
    int r = tid >> 1, part = tid & 1;
    const float4* s4 = reinterpret_cast<const float4*>(pt + r * 136 + part * 64);
    float4* d4 = reinterpret_cast<float4*>(Pb + (size_t)(n0 + r) * HW + m0 + part * 64);
    #pragma unroll
    for (int u = 0; u < 8; u++) d4[u] = s4[u];
}

// ---------------------------------------------------------------------------
// K3: column softmax finalize. Merge tile stats -> per-(tile,col) scale
// factor, then in-place rescale of g_p16.
// ---------------------------------------------------------------------------
__global__ __launch_bounds__(256) void k_softmax()
{
    int b = blockIdx.y;
    int col = threadIdx.x & 63;
    int m = blockIdx.x * 64 + col;
    int rq = threadIdx.x >> 6;
    __half* Pb = g_p16 + (size_t)b * HW * HW;

    float m2s[8];
    float mx = -3.4e38f, den = 0.f;
    #pragma unroll
    for (int t = 0; t < 8; t++) {
        int tn = rq * 8 + t;
        size_t si = ((size_t)b * 32 + tn) * HW + m;
        float m2 = g_cmax[si];
        float d2 = g_csum[si];
        m2s[t] = m2;
        float nm = fmaxf(mx, m2);
        den = den * fast_exp_neg(mx - nm) + d2 * fast_exp_neg(m2 - nm);
        mx = nm;
    }

    __shared__ float smx[256], sden[256];
    __shared__ float cmx[64], cinv[64];
    smx[threadIdx.x] = mx; sden[threadIdx.x] = den;
    __syncthreads();
    if (threadIdx.x < 64) {
        float M = smx[threadIdx.x], D = sden[threadIdx.x];
        #pragma unroll
        for (int k = 1; k < 4; k++) {
            float m2 = smx[threadIdx.x + 64 * k], d2 = sden[threadIdx.x + 64 * k];
            float nm = fmaxf(M, m2);
            D = D * fast_exp_neg(M - nm) + d2 * fast_exp_neg(m2 - nm);
            M = nm;
        }
        cmx[threadIdx.x] = M;
        cinv[threadIdx.x] = 1.0f / D;
    }
    __syncthreads();
    float M = cmx[col], inv = cinv[col];

    #pragma unroll
    for (int t = 0; t < 8; t++) {
        float fac = fast_exp_neg(m2s[t] - M) * inv;
        int base = (rq * 8 + t) * 128;
        for (int n = base; n < base + 128; n += 8) {
            float v[8];
            #pragma unroll
            for (int u = 0; u < 8; u++)
                v[u] = __half2float(Pb[(size_t)(n + u) * HW + m]);
            #pragma unroll
            for (int u = 0; u < 8; u++)
                Pb[(size_t)(n + u) * HW + m] = __float2half_rn(v[u] * fac);
        }
    }
}

// ---------------------------------------------------------------------------
// K4: O = P V (fp16 single product) + residual. K=4096, 64 stages of 64,
// 3-deep cp.async pipeline (wait_group 1).
// ---------------------------------------------------------------------------
__global__ __launch_bounds__(256) void k_out_mma(
    const float* __restrict__ x, float* __restrict__ out)
{
    MMA_PROLOG();
    int b = blockIdx.z;
    int c0 = blockIdx.x * 128;
    int n0 = blockIdx.y * 128;

    const __half* A = g_p16 + (size_t)b * HW * HW + (size_t)n0 * HW;
    const __half* B = g_vt16 + ((size_t)b * CH + c0) * HW;

    stage_load_o64(sb, 0, A, B, HW, HW, 0, tid);
    stage_load_o64(sb, 1, A, B, HW, HW, 64, tid);
    const int KS = HW / 64;
    for (int s = 0; s < KS; s++) {
        cp_wait1();
        __syncthreads();
        if (s + 2 < KS)
            stage_load_o64(sb, (s + 2) % 3, A, B, HW, HW, (s + 2) * 64, tid);
        else
            cp_commit();
        stage_mma_o64(sb + (s % 3) * OT_STAGE_B, acc, wm, wn, lane);
    }

    const float* xb = x + (size_t)b * CH * HW;
    float* ob = out + (size_t)b * CH * HW;
    #pragma unroll
    for (int i = 0; i < 4; i++) {
        int n = n0 + wm * 64 + i * 16 + g;
        #pragma unroll
        for (int j = 0; j < 4; j++) {
            int c = c0 + wn * 32 + j * 8 + tg * 2;
            {
                size_t off = (size_t)n * CH + c;
                float2 xv = *reinterpret_cast<const float2*>(&xb[off]);
                *reinterpret_cast<float2*>(&ob[off]) =
                    make_float2(fmaf(0.1f, acc[i][j][0], xv.x),
                                fmaf(0.1f, acc[i][j][1], xv.y));
            }
            {
                size_t off = (size_t)(n + 8) * CH + c;
                float2 xv = *reinterpret_cast<const float2*>(&xb[off]);
                *reinterpret_cast<float2*>(&ob[off]) =
                    make_float2(fmaf(0.1f, acc[i][j][2], xv.x),
                                fmaf(0.1f, acc[i][j][3], xv.y));
            }
        }
    }
}

// ---------------------------------------------------------------------------
extern "C" void kernel_launch(void* const* d_in, const int* in_sizes, int n_in,
                              void* d_out, int out_size)
{
    const float* x  = (const float*)d_in[0];
    const float* Wq = (const float*)d_in[1];
    const float* bq = (const float*)d_in[2];
    const float* Wk = (const float*)d_in[3];
    const float* bk = (const float*)d_in[4];
    const float* Wv = (const float*)d_in[5];
    const float* bv = (const float*)d_in[6];
    float* out = (float*)d_out;

    static int configured = 0;
    if (!configured) {
        cudaFuncSetAttribute(k_proj_mma,   cudaFuncAttributeMaxDynamicSharedMemorySize, SMEM_GEMM);
        cudaFuncSetAttribute(k_scores_mma, cudaFuncAttributeMaxDynamicSharedMemorySize, SC_SMEM);
        cudaFuncSetAttribute(k_out_mma,    cudaFuncAttributeMaxDynamicSharedMemorySize, OT_SMEM);
        configured = 1;
    }

    k_split_x   <<<dim3(HW / 32, CH / 32, BATCH), 256>>>(x);
    k_split_w   <<<dim3(AD * CH / 256, 3), 256>>>(Wq, Wk, Wv);
    k_proj_mma  <<<dim3(HW / 128, AD / 128, BATCH * 3), 256, SMEM_GEMM>>>(bq, bk, bv);
    k_scores_mma<<<dim3(HW / 128, HW / 128, BATCH), 256, SC_SMEM>>>();
    k_softmax   <<<dim3(HW / 64, BATCH), 256>>>();
    k_out_mma   <<<dim3(CH / 128, HW / 128, BATCH), 256, OT_SMEM>>>(x, out);
}